// round 12
// baseline (speedup 1.0000x reference)
#include <cuda_runtime.h>
#include <cstdint>
#include <math.h>

#define B 32
#define T 256
#define DI 512
#define H 1024
#define G4 (4*H)
#define G5 (5*H)
#define TBH ((size_t)T*(size_t)B*(size_t)H)
#define NBLK 128
#define WSS 257   // ws row stride in float4 (bank-conflict-free padding)

typedef unsigned long long ull;

// Scratch (allocation-free: __device__ globals)
__device__ float g_pre[(size_t)T*B*G5];     // gate pre-activations
__device__ float g_hbuf[2*TBH];             // ping-pong h sequences, layout (t,b,j)
__device__ float g_cbuf[2*TBH];             // ping-pong c sequences

// Producer-group counters: group q = blocks 32q..32q+31 produce k-chunk q.
// Monotone within a launch; reset by reset_ctrs before each scan kernel.
__device__ unsigned g_cnt4[4];

__device__ __forceinline__ float sigf(float x) { return 1.0f / (1.0f + __expf(-x)); }

__device__ __forceinline__ void fma2(ull& d, ull a, ull b) {
    asm("fma.rn.f32x2 %0, %1, %2, %0;" : "+l"(d) : "l"(a), "l"(b));
}
__device__ __forceinline__ ull packdup(float x) {
    ull r; asm("mov.b64 %0, {%1, %1};" : "=l"(r) : "f"(x)); return r;
}
__device__ __forceinline__ float2 unpack2(ull v) {
    float2 f; asm("mov.b64 {%0, %1}, %2;" : "=f"(f.x), "=f"(f.y) : "l"(v)); return f;
}
__device__ __forceinline__ unsigned smem_u32(const void* p) {
    return (unsigned)__cvta_generic_to_shared(p);
}
__device__ __forceinline__ void cpasync16(unsigned dst, const void* src) {
    asm volatile("cp.async.cg.shared.global [%0], [%1], 16;" :: "r"(dst), "l"(src));
}
__device__ __forceinline__ void cpcommit() {
    asm volatile("cp.async.commit_group;");
}
template<int N> __device__ __forceinline__ void waitg() {
    asm volatile("cp.async.wait_group %0;" :: "n"(N));
}

// Warp-level poll: lane 0 spins until group q's counter reaches `need`.
__device__ __forceinline__ void pollw(int q, unsigned need) {
    if ((threadIdx.x & 31) == 0) {
        unsigned v;
        for (;;) {
            asm volatile("ld.global.acquire.gpu.u32 %0, [%1];"
                         : "=r"(v) : "l"(&g_cnt4[q]) : "memory");
            if (v >= need) break;
            __nanosleep(64);
        }
    }
    __syncwarp();
}

// Stage one 256-k chunk (32KB) of h[t-1] into a smem buffer (pad-33 layout).
__device__ __forceinline__ void stage_chunk(unsigned bufu, const float* hprev, int kc, int tid) {
#pragma unroll
    for (int it2 = 0; it2 < 4; it2++) {
        int i = tid + it2 * 512;
        int bb = i >> 6, kql = i & 63;
        cpasync16(bufu + (unsigned)(kql * 33 + bb) * 16,
                  hprev + (size_t)bb * H + kc + kql * 4);
    }
    cpcommit();
}

// MAC over one chunk (64 kq of float4) from buf; kq0 = global kq base.
template<int NG>
__device__ __forceinline__ void chunk_mac(const float4* ws4, const float4* buf,
                                          ull (&acc)[NG][4], int kq0, int kh, int jj, int bg)
{
#pragma unroll 4
    for (int it = 0; it < 8; it++) {
        int kq = kh + it * 8;
        ulonglong2 hv0 = *reinterpret_cast<const ulonglong2*>(&buf[kq * 33 + bg]);
        ulonglong2 hv1 = *reinterpret_cast<const ulonglong2*>(&buf[kq * 33 + bg + 8]);
        ulonglong2 hv2 = *reinterpret_cast<const ulonglong2*>(&buf[kq * 33 + bg + 16]);
        ulonglong2 hv3 = *reinterpret_cast<const ulonglong2*>(&buf[kq * 33 + bg + 24]);
        int kqg = kq0 + kq;
#pragma unroll
        for (int g = 0; g < NG; g++) {
            ulonglong2 wv = *reinterpret_cast<const ulonglong2*>(&ws4[(g * 8 + jj) * WSS + kqg]);
            fma2(acc[g][0], wv.x, hv0.x); fma2(acc[g][0], wv.y, hv0.y);
            fma2(acc[g][1], wv.x, hv1.x); fma2(acc[g][1], wv.y, hv1.y);
            fma2(acc[g][2], wv.x, hv2.x); fma2(acc[g][2], wv.y, hv2.y);
            fma2(acc[g][3], wv.x, hv3.x); fma2(acc[g][3], wv.y, hv3.y);
        }
    }
}

__global__ void reset_ctrs() {
    if (threadIdx.x < 4) g_cnt4[threadIdx.x] = 0;
}

// ---------------------------------------------------------------------------
// GEMM: C[row(m)][n] = sum_k A[m][k] * W[n][k] + b0[n] (+ b1[n])
// ---------------------------------------------------------------------------
__global__ __launch_bounds__(256) void gemm_bias(
    const float* __restrict__ A, int lda,
    const float* __restrict__ W, int ldw,
    const float* __restrict__ b0, const float* __restrict__ b1,
    float* __restrict__ C, int ldc, int K, int swapMT)
{
    __shared__ float As[8][128];
    __shared__ float Bs[8][128];

    const int tid = threadIdx.x;
    const int m0 = blockIdx.y * 128;
    const int n0 = blockIdx.x * 128;
    const int tx = tid & 15;
    const int ty = tid >> 4;

    const int ar = tid >> 1;
    const int ac = (tid & 1) * 4;
    const float* Ap = A + (size_t)(m0 + ar) * lda + ac;
    const float* Wp = W + (size_t)(n0 + ar) * ldw + ac;

    ull acc2[8][4];
#pragma unroll
    for (int i = 0; i < 8; i++)
#pragma unroll
        for (int jp = 0; jp < 4; jp++) acc2[i][jp] = 0ULL;

    for (int k0 = 0; k0 < K; k0 += 8) {
        float4 av = *reinterpret_cast<const float4*>(Ap + k0);
        float4 wv = *reinterpret_cast<const float4*>(Wp + k0);
        __syncthreads();
        As[ac + 0][ar] = av.x; As[ac + 1][ar] = av.y;
        As[ac + 2][ar] = av.z; As[ac + 3][ar] = av.w;
        Bs[ac + 0][ar] = wv.x; Bs[ac + 1][ar] = wv.y;
        Bs[ac + 2][ar] = wv.z; Bs[ac + 3][ar] = wv.w;
        __syncthreads();
#pragma unroll
        for (int kk = 0; kk < 8; kk++) {
            const float4* arow = reinterpret_cast<const float4*>(&As[kk][ty * 8]);
            float4 alo = arow[0], ahi = arow[1];
            const ulonglong2* brow = reinterpret_cast<const ulonglong2*>(&Bs[kk][tx * 8]);
            ulonglong2 b01 = brow[0], b23 = brow[1];
            float a[8] = {alo.x, alo.y, alo.z, alo.w, ahi.x, ahi.y, ahi.z, ahi.w};
#pragma unroll
            for (int i = 0; i < 8; i++) {
                ull ad = packdup(a[i]);
                fma2(acc2[i][0], ad, b01.x);
                fma2(acc2[i][1], ad, b01.y);
                fma2(acc2[i][2], ad, b23.x);
                fma2(acc2[i][3], ad, b23.y);
            }
        }
    }

    const int nb = n0 + tx * 8;
#pragma unroll
    for (int i = 0; i < 8; i++) {
        int m = m0 + ty * 8 + i;
        int row = swapMT ? ((m & (T - 1)) * B + (m >> 8)) : m;
        float* cr = C + (size_t)row * ldc + nb;
#pragma unroll
        for (int jp = 0; jp < 4; jp++) {
            float2 v = unpack2(acc2[i][jp]);
            int n = nb + jp * 2;
            float bi0 = b0[n]     + (b1 ? b1[n]     : 0.0f);
            float bi1 = b0[n + 1] + (b1 ? b1[n + 1] : 0.0f);
            float2 o; o.x = v.x + bi0; o.y = v.y + bi1;
            *reinterpret_cast<float2*>(cr + jp * 2) = o;
        }
    }
}

// ---------------------------------------------------------------------------
// Persistent layer-0 LSTM scan. Barrier-free: group counters + pipelined
// chunk staging (4 chunks x 2 buffers, cp.async double buffering).
// ---------------------------------------------------------------------------
__global__ __launch_bounds__(512) void lstm0_scan(const float* __restrict__ Whh)
{
    extern __shared__ float smemf[];
    float4* ws4  = reinterpret_cast<float4*>(smemf);              // [32][WSS]
    float4* buf0 = reinterpret_cast<float4*>(smemf + 32*WSS*4);   // [64][33]
    float4* buf1 = buf0 + 64 * 33;                                // [64][33]
    float*  red  = smemf + 32*WSS*4;                              // alias buf0

    const int tid = threadIdx.x;
    const int jbase = blockIdx.x * 8;
    const int grp = blockIdx.x >> 5;
    const int w = tid >> 5, kh = w & 7, jj2 = w >> 3;
    const int lane = tid & 31, bg = lane & 7, jjg = lane >> 3;
    const int jj = jj2 * 4 + jjg;

    const int pj8 = tid & 7, pbb = tid >> 3;   // pointwise role (tid<256)
    const int pj = jbase + pj8;
    float creg = 0.0f;
    const unsigned b0u = smem_u32(buf0);
    const unsigned b1u = smem_u32(buf1);

    for (int i = tid; i < 32 * 256; i += 512) {
        int r = i >> 8, kq = i & 255;
        int grow = ((r >> 3) << 10) + jbase + (r & 7);
        ws4[r * WSS + kq] = *reinterpret_cast<const float4*>(Whh + (size_t)grow * H + kq * 4);
    }
    __syncthreads();

    for (int t = 0; t < T; t++) {
        float pg0 = 0, pg1 = 0, pg2 = 0, pg3 = 0;
        size_t idx = 0;
        if (tid < 256) {
            const float* xp = g_pre + ((size_t)t * B + pbb) * G4 + pj;
            pg0 = xp[0]; pg1 = xp[H]; pg2 = xp[2*H]; pg3 = xp[3*H];
            idx = ((size_t)t * B + pbb) * H + pj;
        }

        if (t > 0) {
            ull acc[4][4];
#pragma unroll
            for (int g = 0; g < 4; g++)
#pragma unroll
                for (int i = 0; i < 4; i++) acc[g][i] = 0ULL;

            const float* hprev = g_hbuf + (size_t)(t - 1) * (B * H);
            const unsigned need = 32u * (unsigned)t;

            pollw(0, need); stage_chunk(b0u, hprev, 0,   tid);
            pollw(1, need); stage_chunk(b1u, hprev, 256, tid);
            waitg<1>(); __syncthreads();                 // chunk0 staged
            chunk_mac<4>(ws4, buf0, acc, 0,   kh, jj, bg);
            __syncthreads();                             // buf0 free
            pollw(2, need); stage_chunk(b0u, hprev, 512, tid);
            waitg<1>(); __syncthreads();                 // chunk1 staged
            chunk_mac<4>(ws4, buf1, acc, 64,  kh, jj, bg);
            __syncthreads();                             // buf1 free
            pollw(3, need); stage_chunk(b1u, hprev, 768, tid);
            waitg<1>(); __syncthreads();                 // chunk2 staged
            chunk_mac<4>(ws4, buf0, acc, 128, kh, jj, bg);
            waitg<0>(); __syncthreads();                 // chunk3 staged
            chunk_mac<4>(ws4, buf1, acc, 192, kh, jj, bg);
            __syncthreads();                             // all reads done (red aliases bufs)

#pragma unroll
            for (int g = 0; g < 4; g++)
#pragma unroll
                for (int i = 0; i < 4; i++) {
                    float2 v = unpack2(acc[g][i]);
                    red[((((kh * 2 + jj2) * 4 + g) * 4 + i) * 33) + bg * 4 + jjg] = v.x + v.y;
                }
            __syncthreads();
        }

        if (tid < 256) {
            float sg[4] = {0, 0, 0, 0};
            if (t > 0) {
                const int jj2c = pj8 >> 2, jjgc = pj8 & 3;
                const int ic = pbb >> 3, bgc = pbb & 7;
#pragma unroll
                for (int g = 0; g < 4; g++) {
                    float s = 0.0f;
#pragma unroll
                    for (int k8 = 0; k8 < 8; k8++)
                        s += red[((((k8 * 2 + jj2c) * 4 + g) * 4 + ic) * 33) + bgc * 4 + jjgc];
                    sg[g] = s;
                }
            }
            float gi = sg[0] + pg0, gf = sg[1] + pg1, gg = sg[2] + pg2, go = sg[3] + pg3;
            float cc = sigf(gf) * creg + sigf(gi) * tanhf(gg);
            float hh = sigf(go) * tanhf(cc);
            creg = cc;
            g_hbuf[idx] = hh;
            g_cbuf[idx] = cc;
            __threadfence();        // release own h/c stores
        }
        __syncthreads();            // block's h complete; red consumed
        if (tid == 0 && t < T - 1) atomicAdd(&g_cnt4[grp], 1u);
    }
}

// ---------------------------------------------------------------------------
// Persistent CA-LSTM scan (layers 1..3). Same pipeline, 5 gates.
// ---------------------------------------------------------------------------
__global__ __launch_bounds__(512) void ca_scan(const float* __restrict__ Wp, int src, int dst)
{
    extern __shared__ float smemf[];
    float4* ws4  = reinterpret_cast<float4*>(smemf);              // [40][WSS]
    float4* buf0 = reinterpret_cast<float4*>(smemf + 40*WSS*4);   // [64][33]
    float4* buf1 = buf0 + 64 * 33;
    float*  red  = smemf + 40*WSS*4;                              // alias bufs

    const int tid = threadIdx.x;
    const int jbase = blockIdx.x * 8;
    const int grp = blockIdx.x >> 5;
    const int w = tid >> 5, kh = w & 7, jj2 = w >> 3;
    const int lane = tid & 31, bg = lane & 7, jjg = lane >> 3;
    const int jj = jj2 * 4 + jjg;

    const int pj8 = tid & 7, pbb = tid >> 3;
    const int pj = jbase + pj8;
    float creg = 0.0f;
    const unsigned b0u = smem_u32(buf0);
    const unsigned b1u = smem_u32(buf1);

    for (int i = tid; i < 40 * 256; i += 512) {
        int r = i >> 8, kq = i & 255;
        int grow = (r >> 3) * H + jbase + (r & 7);
        ws4[r * WSS + kq] = *reinterpret_cast<const float4*>(Wp + (size_t)grow * (2 * H) + kq * 4);
    }
    __syncthreads();

    for (int t = 0; t < T; t++) {
        float pg0 = 0, pg1 = 0, pg2 = 0, pg3 = 0, pg4 = 0, cl = 0;
        size_t idx = 0;
        if (tid < 256) {
            const float* pre = g_pre + ((size_t)t * B + pbb) * G5 + pj;
            pg0 = pre[0]; pg1 = pre[H]; pg2 = pre[2*H]; pg3 = pre[3*H]; pg4 = pre[4*H];
            idx = ((size_t)t * B + pbb) * H + pj;
            cl = g_cbuf[(size_t)src * TBH + idx];
        }

        if (t > 0) {
            ull acc[5][4];
#pragma unroll
            for (int g = 0; g < 5; g++)
#pragma unroll
                for (int i = 0; i < 4; i++) acc[g][i] = 0ULL;

            const float* hprev = g_hbuf + (size_t)dst * TBH + (size_t)(t - 1) * (B * H);
            const unsigned need = 32u * (unsigned)t;

            pollw(0, need); stage_chunk(b0u, hprev, 0,   tid);
            pollw(1, need); stage_chunk(b1u, hprev, 256, tid);
            waitg<1>(); __syncthreads();
            chunk_mac<5>(ws4, buf0, acc, 0,   kh, jj, bg);
            __syncthreads();
            pollw(2, need); stage_chunk(b0u, hprev, 512, tid);
            waitg<1>(); __syncthreads();
            chunk_mac<5>(ws4, buf1, acc, 64,  kh, jj, bg);
            __syncthreads();
            pollw(3, need); stage_chunk(b1u, hprev, 768, tid);
            waitg<1>(); __syncthreads();
            chunk_mac<5>(ws4, buf0, acc, 128, kh, jj, bg);
            waitg<0>(); __syncthreads();
            chunk_mac<5>(ws4, buf1, acc, 192, kh, jj, bg);
            __syncthreads();

#pragma unroll
            for (int g = 0; g < 5; g++)
#pragma unroll
                for (int i = 0; i < 4; i++) {
                    float2 v = unpack2(acc[g][i]);
                    red[((((kh * 2 + jj2) * 5 + g) * 4 + i) * 33) + bg * 4 + jjg] = v.x + v.y;
                }
            __syncthreads();
        }

        if (tid < 256) {
            float sg[5] = {0, 0, 0, 0, 0};
            if (t > 0) {
                const int jj2c = pj8 >> 2, jjgc = pj8 & 3;
                const int ic = pbb >> 3, bgc = pbb & 7;
#pragma unroll
                for (int g = 0; g < 5; g++) {
                    float s = 0.0f;
#pragma unroll
                    for (int k8 = 0; k8 < 8; k8++)
                        s += red[((((k8 * 2 + jj2c) * 5 + g) * 4 + ic) * 33) + bgc * 4 + jjgc];
                    sg[g] = s;
                }
            }
            float gi  = sg[0] + pg0;
            float gfp = sg[1] + pg1;
            float gfl = sg[2] + pg2;
            float gu  = sg[3] + pg3;
            float go  = sg[4] + pg4;
            float cc = creg * sigf(gfp + 1.0f) + cl * sigf(gfl + 1.0f) + tanhf(gu) * sigf(gi);
            float hh = sigf(go) * tanhf(cc);
            creg = cc;
            g_hbuf[(size_t)dst * TBH + idx] = hh;
            g_cbuf[(size_t)dst * TBH + idx] = cc;
            __threadfence();
        }
        __syncthreads();
        if (tid == 0 && t < T - 1) atomicAdd(&g_cnt4[grp], 1u);
    }
}

// ---------------------------------------------------------------------------
// Final transpose (t,b,j) -> (b,t,j); h then c into d_out.
// ---------------------------------------------------------------------------
__global__ __launch_bounds__(256) void finalize(int fin, float* __restrict__ out)
{
    size_t gid = (size_t)blockIdx.x * 256 + threadIdx.x;
    int j = (int)(gid & (H - 1));
    int bt = (int)(gid >> 10);
    int t = bt & (T - 1);
    int b = bt >> 8;
    size_t srci = ((size_t)t * B + b) * H + j;
    out[gid]       = g_hbuf[(size_t)fin * TBH + srci];
    out[TBH + gid] = g_cbuf[(size_t)fin * TBH + srci];
}

// ---------------------------------------------------------------------------
extern "C" void kernel_launch(void* const* d_in, const int* in_sizes, int n_in,
                              void* d_out, int out_size)
{
    (void)in_sizes; (void)n_in; (void)out_size;
    const float* inputs = (const float*)d_in[0];
    const float* W_ih0  = (const float*)d_in[1];
    const float* W_hh0  = (const float*)d_in[2];
    const float* b_ih0  = (const float*)d_in[3];
    const float* b_hh0  = (const float*)d_in[4];
    const float* W_ca   = (const float*)d_in[5];
    const float* b_ca   = (const float*)d_in[6];
    float* out = (float*)d_out;

    float* pre = nullptr;
    float* hb  = nullptr;
    cudaGetSymbolAddress((void**)&pre, g_pre);
    cudaGetSymbolAddress((void**)&hb,  g_hbuf);

    const int smem0 = 32 * WSS * 16 + 2 * 64 * 33 * 16;   // 199168
    const int smemC = 40 * WSS * 16 + 2 * 64 * 33 * 16;   // 232064
    cudaFuncSetAttribute(lstm0_scan, cudaFuncAttributeMaxDynamicSharedMemorySize, smem0);
    cudaFuncSetAttribute(ca_scan,    cudaFuncAttributeMaxDynamicSharedMemorySize, smemC);

    gemm_bias<<<dim3(G4 / 128, (B * T) / 128), 256>>>(
        inputs, DI, W_ih0, DI, b_ih0, b_hh0, pre, G4, DI, 1);
    reset_ctrs<<<1, 32>>>();
    lstm0_scan<<<NBLK, 512, smem0>>>(W_hh0);

    int src = 0;
    for (int l = 0; l < 3; l++) {
        int dst = 1 - src;
        gemm_bias<<<dim3(G5 / 128, (B * T) / 128), 256>>>(
            hb + (size_t)src * TBH, H,
            W_ca + (size_t)l * G5 * (2 * H), 2 * H,
            b_ca + (size_t)l * G5, nullptr,
            pre, G5, H, 0);
        reset_ctrs<<<1, 32>>>();
        ca_scan<<<NBLK, 512, smemC>>>(W_ca + (size_t)l * G5 * (2 * H) + H, src, dst);
        src = dst;
    }

    finalize<<<(int)(TBH / 256), 256>>>(src, out);
}

// round 13
// speedup vs baseline: 1.2553x; 1.2553x over previous
#include <cuda_runtime.h>
#include <cstdint>
#include <math.h>

#define B 32
#define T 256
#define DI 512
#define H 1024
#define G4 (4*H)
#define G5 (5*H)
#define TBH ((size_t)T*(size_t)B*(size_t)H)
#define THB ((size_t)T*(size_t)(H*B))
#define NBLK 128
#define WSS 257        // ws row stride in float4 (bank-conflict-free padding)
#define CB  32768u     // chunk bytes (256 k x 32 b x 4B)

typedef unsigned long long ull;

// Scratch (allocation-free: __device__ globals)
__device__ float g_pre[(size_t)T*B*G5];     // gate pre-activations
__device__ float g_hbuf[2*TBH];             // ping-pong h, layout (t,b,j) (GEMM/finalize)
__device__ float g_cbuf[2*TBH];             // ping-pong c, layout (t,b,j)
__device__ float g_hT[2*THB];               // ping-pong h, layout (t, j>>1, b, j&1) for TMA

// Grid barrier state
__device__ unsigned g_cnt;
__device__ volatile unsigned g_gen;

__device__ __forceinline__ float sigf(float x) { return 1.0f / (1.0f + __expf(-x)); }

__device__ __forceinline__ void fma2(ull& d, ull a, ull b) {
    asm("fma.rn.f32x2 %0, %1, %2, %0;" : "+l"(d) : "l"(a), "l"(b));
}
__device__ __forceinline__ ull packdup(float x) {
    ull r; asm("mov.b64 %0, {%1, %1};" : "=l"(r) : "f"(x)); return r;
}
__device__ __forceinline__ float2 unpack2(ull v) {
    float2 f; asm("mov.b64 {%0, %1}, %2;" : "=f"(f.x), "=f"(f.y) : "l"(v)); return f;
}
__device__ __forceinline__ unsigned smem_u32(const void* p) {
    return (unsigned)__cvta_generic_to_shared(p);
}

// ---- mbarrier + bulk-copy helpers -----------------------------------------
__device__ __forceinline__ void mbar_init(unsigned a, unsigned cnt) {
    asm volatile("mbarrier.init.shared.b64 [%0], %1;" :: "r"(a), "r"(cnt) : "memory");
}
__device__ __forceinline__ void mbar_expect(unsigned a, unsigned tx) {
    asm volatile("mbarrier.arrive.expect_tx.shared.b64 _, [%0], %1;" :: "r"(a), "r"(tx) : "memory");
}
__device__ __forceinline__ void mbar_wait(unsigned a, unsigned ph) {
    unsigned done = 0;
    while (!done) {
        asm volatile(
            "{\n\t.reg .pred p;\n\t"
            "mbarrier.try_wait.parity.acquire.cta.shared::cta.b64 p, [%1], %2;\n\t"
            "selp.b32 %0, 1, 0, p;\n\t}"
            : "=r"(done) : "r"(a), "r"(ph) : "memory");
        if (!done) __nanosleep(32);
    }
}
__device__ __forceinline__ void tma_bulk(unsigned dst, const void* src, unsigned bytes, unsigned mbar) {
    asm volatile("fence.proxy.async.shared::cta;" ::: "memory");
    asm volatile(
        "cp.async.bulk.shared::cluster.global.mbarrier::complete_tx::bytes [%0], [%1], %2, [%3];"
        :: "r"(dst), "l"(src), "r"(bytes), "r"(mbar) : "memory");
}

// All-blocks barrier (R11-proven).
__device__ __forceinline__ void grid_bar()
{
    __syncthreads();
    if (threadIdx.x == 0) {
        __threadfence();
        unsigned my = g_gen;
        if (atomicAdd(&g_cnt, 1u) == NBLK - 1) {
            atomicExch(&g_cnt, 0u);
            __threadfence();
            g_gen = my + 1;
        } else {
            while (g_gen == my) { __nanosleep(32); }
            __threadfence();
        }
    }
    __syncthreads();
}

// MAC over one 256-k chunk held as bu[kq2][b] (ull = k-pair). q = float4-k in
// chunk (0..63), covers kq2 = 2q, 2q+1. Thread b-set: {2bg, 2bg+1, 2bg+16, 2bg+17}.
template<int NG>
__device__ __forceinline__ void chunk_mac(const float4* ws4, const ull* bu,
                                          ull (&acc)[NG][4], int kq4base, int kh, int jj, int bg)
{
#pragma unroll 4
    for (int it = 0; it < 8; it++) {
        int q = kh + it * 8;
        const ull* r = bu + (q * 64);
        ulonglong2 ha = *reinterpret_cast<const ulonglong2*>(r + 2 * bg);
        ulonglong2 hc = *reinterpret_cast<const ulonglong2*>(r + 2 * bg + 16);
        ulonglong2 hb = *reinterpret_cast<const ulonglong2*>(r + 32 + 2 * bg);
        ulonglong2 hd = *reinterpret_cast<const ulonglong2*>(r + 32 + 2 * bg + 16);
        int kqg = kq4base + q;
#pragma unroll
        for (int g = 0; g < NG; g++) {
            ulonglong2 wv = *reinterpret_cast<const ulonglong2*>(&ws4[(g * 8 + jj) * WSS + kqg]);
            fma2(acc[g][0], wv.x, ha.x); fma2(acc[g][1], wv.x, ha.y);
            fma2(acc[g][2], wv.x, hc.x); fma2(acc[g][3], wv.x, hc.y);
            fma2(acc[g][0], wv.y, hb.x); fma2(acc[g][1], wv.y, hb.y);
            fma2(acc[g][2], wv.y, hd.x); fma2(acc[g][3], wv.y, hd.y);
        }
    }
}

// ---------------------------------------------------------------------------
// GEMM: C[row(m)][n] = sum_k A[m][k] * W[n][k] + b0[n] (+ b1[n])
// ---------------------------------------------------------------------------
__global__ __launch_bounds__(256) void gemm_bias(
    const float* __restrict__ A, int lda,
    const float* __restrict__ W, int ldw,
    const float* __restrict__ b0, const float* __restrict__ b1,
    float* __restrict__ C, int ldc, int K, int swapMT)
{
    __shared__ float As[8][128];
    __shared__ float Bs[8][128];

    const int tid = threadIdx.x;
    const int m0 = blockIdx.y * 128;
    const int n0 = blockIdx.x * 128;
    const int tx = tid & 15;
    const int ty = tid >> 4;

    const int ar = tid >> 1;
    const int ac = (tid & 1) * 4;
    const float* Ap = A + (size_t)(m0 + ar) * lda + ac;
    const float* Wp = W + (size_t)(n0 + ar) * ldw + ac;

    ull acc2[8][4];
#pragma unroll
    for (int i = 0; i < 8; i++)
#pragma unroll
        for (int jp = 0; jp < 4; jp++) acc2[i][jp] = 0ULL;

    for (int k0 = 0; k0 < K; k0 += 8) {
        float4 av = *reinterpret_cast<const float4*>(Ap + k0);
        float4 wv = *reinterpret_cast<const float4*>(Wp + k0);
        __syncthreads();
        As[ac + 0][ar] = av.x; As[ac + 1][ar] = av.y;
        As[ac + 2][ar] = av.z; As[ac + 3][ar] = av.w;
        Bs[ac + 0][ar] = wv.x; Bs[ac + 1][ar] = wv.y;
        Bs[ac + 2][ar] = wv.z; Bs[ac + 3][ar] = wv.w;
        __syncthreads();
#pragma unroll
        for (int kk = 0; kk < 8; kk++) {
            const float4* arow = reinterpret_cast<const float4*>(&As[kk][ty * 8]);
            float4 alo = arow[0], ahi = arow[1];
            const ulonglong2* brow = reinterpret_cast<const ulonglong2*>(&Bs[kk][tx * 8]);
            ulonglong2 b01 = brow[0], b23 = brow[1];
            float a[8] = {alo.x, alo.y, alo.z, alo.w, ahi.x, ahi.y, ahi.z, ahi.w};
#pragma unroll
            for (int i = 0; i < 8; i++) {
                ull ad = packdup(a[i]);
                fma2(acc2[i][0], ad, b01.x);
                fma2(acc2[i][1], ad, b01.y);
                fma2(acc2[i][2], ad, b23.x);
                fma2(acc2[i][3], ad, b23.y);
            }
        }
    }

    const int nb = n0 + tx * 8;
#pragma unroll
    for (int i = 0; i < 8; i++) {
        int m = m0 + ty * 8 + i;
        int row = swapMT ? ((m & (T - 1)) * B + (m >> 8)) : m;
        float* cr = C + (size_t)row * ldc + nb;
#pragma unroll
        for (int jp = 0; jp < 4; jp++) {
            float2 v = unpack2(acc2[i][jp]);
            int n = nb + jp * 2;
            float bi0 = b0[n]     + (b1 ? b1[n]     : 0.0f);
            float bi1 = b0[n + 1] + (b1 ? b1[n + 1] : 0.0f);
            float2 o; o.x = v.x + bi0; o.y = v.y + bi1;
            *reinterpret_cast<float2*>(cr + jp * 2) = o;
        }
    }
}

// ---------------------------------------------------------------------------
// Persistent scans. smem: [0..32) mbar/pad, ws [NG*8][WSS] f4, 2x 32KB bufs.
// h staged via cp.async.bulk (UBLKCP) from g_hT, double-buffered.
// ---------------------------------------------------------------------------
__global__ __launch_bounds__(512) void lstm0_scan(const float* __restrict__ Whh)
{
    extern __shared__ float smemf[];
    float4* ws4 = reinterpret_cast<float4*>(smemf + 32);          // [32][WSS]
    ull* bu0 = reinterpret_cast<ull*>(smemf + 32 + 32 * WSS * 4); // 32KB
    ull* bu1 = bu0 + 4096;                                        // 32KB
    float* red = reinterpret_cast<float*>(bu0);                   // alias

    const int tid = threadIdx.x;
    const int jbase = blockIdx.x * 8;
    const int w = tid >> 5, kh = w & 7, jj2 = w >> 3;
    const int lane = tid & 31, bg = lane & 7, jjg = lane >> 3;
    const int jj = jj2 * 4 + jjg;

    const int pj8 = tid & 7, pbb = tid >> 3;   // pointwise role (tid<256)
    const int pj = jbase + pj8;
    float creg = 0.0f;
    const unsigned mb0 = smem_u32(smemf), mb1 = mb0 + 8;
    const unsigned b0u = smem_u32(bu0), b1u = smem_u32(bu1);
    unsigned ph0 = 0, ph1 = 0;

    if (tid == 0) { mbar_init(mb0, 1); mbar_init(mb1, 1); }
    for (int i = tid; i < 32 * 256; i += 512) {
        int r = i >> 8, kq = i & 255;
        int grow = ((r >> 3) << 10) + jbase + (r & 7);
        ws4[r * WSS + kq] = *reinterpret_cast<const float4*>(Whh + (size_t)grow * H + kq * 4);
    }
    __syncthreads();

    for (int t = 0; t < T; t++) {
        float pg0 = 0, pg1 = 0, pg2 = 0, pg3 = 0;
        size_t idx = 0;
        if (tid < 256) {
            const float* xp = g_pre + ((size_t)t * B + pbb) * G4 + pj;
            pg0 = xp[0]; pg1 = xp[H]; pg2 = xp[2*H]; pg3 = xp[3*H];
            idx = ((size_t)t * B + pbb) * H + pj;
        }

        if (t > 0) {
            ull acc[4][4];
#pragma unroll
            for (int g = 0; g < 4; g++)
#pragma unroll
                for (int i = 0; i < 4; i++) acc[g][i] = 0ULL;

            const float* src = g_hT + (size_t)(t - 1) * (H * B);
            if (tid == 0) {
                mbar_expect(mb0, CB); tma_bulk(b0u, src,        CB, mb0);
                mbar_expect(mb1, CB); tma_bulk(b1u, src + 8192, CB, mb1);
            }
            mbar_wait(mb0, ph0); ph0 ^= 1;
            chunk_mac<4>(ws4, bu0, acc, 0, kh, jj, bg);
            __syncthreads();
            if (tid == 0) { mbar_expect(mb0, CB); tma_bulk(b0u, src + 16384, CB, mb0); }
            mbar_wait(mb1, ph1); ph1 ^= 1;
            chunk_mac<4>(ws4, bu1, acc, 64, kh, jj, bg);
            __syncthreads();
            if (tid == 0) { mbar_expect(mb1, CB); tma_bulk(b1u, src + 24576, CB, mb1); }
            mbar_wait(mb0, ph0); ph0 ^= 1;
            chunk_mac<4>(ws4, bu0, acc, 128, kh, jj, bg);
            mbar_wait(mb1, ph1); ph1 ^= 1;
            chunk_mac<4>(ws4, bu1, acc, 192, kh, jj, bg);
            __syncthreads();   // all buf reads done before red (aliases bufs)

#pragma unroll
            for (int g = 0; g < 4; g++)
#pragma unroll
                for (int i = 0; i < 4; i++) {
                    float2 v = unpack2(acc[g][i]);
                    red[((((kh * 2 + jj2) * 4 + g) * 4 + i) * 33) + bg * 4 + jjg] = v.x + v.y;
                }
            __syncthreads();
        }

        if (tid < 256) {
            float sg[4] = {0, 0, 0, 0};
            if (t > 0) {
                const int jj2c = pj8 >> 2, jjgc = pj8 & 3;
                const int bgc = (pbb & 15) >> 1;
                const int ic = (pbb & 1) | (((pbb >> 4) & 1) << 1);
#pragma unroll
                for (int g = 0; g < 4; g++) {
                    float s = 0.0f;
#pragma unroll
                    for (int k8 = 0; k8 < 8; k8++)
                        s += red[((((k8 * 2 + jj2c) * 4 + g) * 4 + ic) * 33) + bgc * 4 + jjgc];
                    sg[g] = s;
                }
            }
            float gi = sg[0] + pg0, gf = sg[1] + pg1, gg = sg[2] + pg2, go = sg[3] + pg3;
            float cc = sigf(gf) * creg + sigf(gi) * tanhf(gg);
            float hh = sigf(go) * tanhf(cc);
            creg = cc;
            g_hbuf[idx] = hh;
            g_cbuf[idx] = cc;
            g_hT[(size_t)t * (H * B) + (size_t)((pj >> 1) * 32 + pbb) * 2 + (pj & 1)] = hh;
        }

        if (t < T - 1) grid_bar();
    }
}

__global__ __launch_bounds__(512) void ca_scan(const float* __restrict__ Wp, int src_s, int dst)
{
    extern __shared__ float smemf[];
    float4* ws4 = reinterpret_cast<float4*>(smemf + 32);          // [40][WSS]
    ull* bu0 = reinterpret_cast<ull*>(smemf + 32 + 40 * WSS * 4);
    ull* bu1 = bu0 + 4096;
    float* red = reinterpret_cast<float*>(bu0);

    const int tid = threadIdx.x;
    const int jbase = blockIdx.x * 8;
    const int w = tid >> 5, kh = w & 7, jj2 = w >> 3;
    const int lane = tid & 31, bg = lane & 7, jjg = lane >> 3;
    const int jj = jj2 * 4 + jjg;

    const int pj8 = tid & 7, pbb = tid >> 3;
    const int pj = jbase + pj8;
    float creg = 0.0f;
    const unsigned mb0 = smem_u32(smemf), mb1 = mb0 + 8;
    const unsigned b0u = smem_u32(bu0), b1u = smem_u32(bu1);
    unsigned ph0 = 0, ph1 = 0;

    if (tid == 0) { mbar_init(mb0, 1); mbar_init(mb1, 1); }
    for (int i = tid; i < 40 * 256; i += 512) {
        int r = i >> 8, kq = i & 255;
        int grow = (r >> 3) * H + jbase + (r & 7);
        ws4[r * WSS + kq] = *reinterpret_cast<const float4*>(Wp + (size_t)grow * (2 * H) + kq * 4);
    }
    __syncthreads();

    for (int t = 0; t < T; t++) {
        float pg0 = 0, pg1 = 0, pg2 = 0, pg3 = 0, pg4 = 0, cl = 0;
        size_t idx = 0;
        if (tid < 256) {
            const float* pre = g_pre + ((size_t)t * B + pbb) * G5 + pj;
            pg0 = pre[0]; pg1 = pre[H]; pg2 = pre[2*H]; pg3 = pre[3*H]; pg4 = pre[4*H];
            idx = ((size_t)t * B + pbb) * H + pj;
            cl = g_cbuf[(size_t)src_s * TBH + idx];
        }

        if (t > 0) {
            ull acc[5][4];
#pragma unroll
            for (int g = 0; g < 5; g++)
#pragma unroll
                for (int i = 0; i < 4; i++) acc[g][i] = 0ULL;

            const float* src = g_hT + (size_t)dst * THB + (size_t)(t - 1) * (H * B);
            if (tid == 0) {
                mbar_expect(mb0, CB); tma_bulk(b0u, src,        CB, mb0);
                mbar_expect(mb1, CB); tma_bulk(b1u, src + 8192, CB, mb1);
            }
            mbar_wait(mb0, ph0); ph0 ^= 1;
            chunk_mac<5>(ws4, bu0, acc, 0, kh, jj, bg);
            __syncthreads();
            if (tid == 0) { mbar_expect(mb0, CB); tma_bulk(b0u, src + 16384, CB, mb0); }
            mbar_wait(mb1, ph1); ph1 ^= 1;
            chunk_mac<5>(ws4, bu1, acc, 64, kh, jj, bg);
            __syncthreads();
            if (tid == 0) { mbar_expect(mb1, CB); tma_bulk(b1u, src + 24576, CB, mb1); }
            mbar_wait(mb0, ph0); ph0 ^= 1;
            chunk_mac<5>(ws4, bu0, acc, 128, kh, jj, bg);
            mbar_wait(mb1, ph1); ph1 ^= 1;
            chunk_mac<5>(ws4, bu1, acc, 192, kh, jj, bg);
            __syncthreads();

#pragma unroll
            for (int g = 0; g < 5; g++)
#pragma unroll
                for (int i = 0; i < 4; i++) {
                    float2 v = unpack2(acc[g][i]);
                    red[((((kh * 2 + jj2) * 5 + g) * 4 + i) * 33) + bg * 4 + jjg] = v.x + v.y;
                }
            __syncthreads();
        }

        if (tid < 256) {
            float sg[5] = {0, 0, 0, 0, 0};
            if (t > 0) {
                const int jj2c = pj8 >> 2, jjgc = pj8 & 3;
                const int bgc = (pbb & 15) >> 1;
                const int ic = (pbb & 1) | (((pbb >> 4) & 1) << 1);
#pragma unroll
                for (int g = 0; g < 5; g++) {
                    float s = 0.0f;
#pragma unroll
                    for (int k8 = 0; k8 < 8; k8++)
                        s += red[((((k8 * 2 + jj2c) * 5 + g) * 4 + ic) * 33) + bgc * 4 + jjgc];
                    sg[g] = s;
                }
            }
            float gi  = sg[0] + pg0;
            float gfp = sg[1] + pg1;
            float gfl = sg[2] + pg2;
            float gu  = sg[3] + pg3;
            float go  = sg[4] + pg4;
            float cc = creg * sigf(gfp + 1.0f) + cl * sigf(gfl + 1.0f) + tanhf(gu) * sigf(gi);
            float hh = sigf(go) * tanhf(cc);
            creg = cc;
            g_hbuf[(size_t)dst * TBH + idx] = hh;
            g_cbuf[(size_t)dst * TBH + idx] = cc;
            g_hT[(size_t)dst * THB + (size_t)t * (H * B) + (size_t)((pj >> 1) * 32 + pbb) * 2 + (pj & 1)] = hh;
        }

        if (t < T - 1) grid_bar();
    }
}

// ---------------------------------------------------------------------------
// Final transpose (t,b,j) -> (b,t,j); h then c into d_out.
// ---------------------------------------------------------------------------
__global__ __launch_bounds__(256) void finalize(int fin, float* __restrict__ out)
{
    size_t gid = (size_t)blockIdx.x * 256 + threadIdx.x;
    int j = (int)(gid & (H - 1));
    int bt = (int)(gid >> 10);
    int t = bt & (T - 1);
    int b = bt >> 8;
    size_t srci = ((size_t)t * B + b) * H + j;
    out[gid]       = g_hbuf[(size_t)fin * TBH + srci];
    out[TBH + gid] = g_cbuf[(size_t)fin * TBH + srci];
}

// ---------------------------------------------------------------------------
extern "C" void kernel_launch(void* const* d_in, const int* in_sizes, int n_in,
                              void* d_out, int out_size)
{
    (void)in_sizes; (void)n_in; (void)out_size;
    const float* inputs = (const float*)d_in[0];
    const float* W_ih0  = (const float*)d_in[1];
    const float* W_hh0  = (const float*)d_in[2];
    const float* b_ih0  = (const float*)d_in[3];
    const float* b_hh0  = (const float*)d_in[4];
    const float* W_ca   = (const float*)d_in[5];
    const float* b_ca   = (const float*)d_in[6];
    float* out = (float*)d_out;

    float* pre = nullptr;
    float* hb  = nullptr;
    cudaGetSymbolAddress((void**)&pre, g_pre);
    cudaGetSymbolAddress((void**)&hb,  g_hbuf);

    const int smem0 = (32 + 32 * WSS * 4) * 4 + 2 * 32768;   // 197,248
    const int smemC = (32 + 40 * WSS * 4) * 4 + 2 * 32768;   // 230,144
    cudaFuncSetAttribute(lstm0_scan, cudaFuncAttributeMaxDynamicSharedMemorySize, smem0);
    cudaFuncSetAttribute(ca_scan,    cudaFuncAttributeMaxDynamicSharedMemorySize, smemC);

    gemm_bias<<<dim3(G4 / 128, (B * T) / 128), 256>>>(
        inputs, DI, W_ih0, DI, b_ih0, b_hh0, pre, G4, DI, 1);
    lstm0_scan<<<NBLK, 512, smem0>>>(W_hh0);

    int src = 0;
    for (int l = 0; l < 3; l++) {
        int dst = 1 - src;
        gemm_bias<<<dim3(G5 / 128, (B * T) / 128), 256>>>(
            hb + (size_t)src * TBH, H,
            W_ca + (size_t)l * G5 * (2 * H), 2 * H,
            b_ca + (size_t)l * G5, nullptr,
            pre, G5, H, 0);
        ca_scan<<<NBLK, 512, smemC>>>(W_ca + (size_t)l * G5 * (2 * H) + H, src, dst);
        src = dst;
    }

    finalize<<<(int)(TBH / 256), 256>>>(src, out);
}

// round 14
// speedup vs baseline: 1.2629x; 1.0060x over previous
#include <cuda_runtime.h>
#include <cstdint>
#include <math.h>

#define B 32
#define T 256
#define DI 512
#define H 1024
#define G4 (4*H)
#define G5 (5*H)
#define TBH ((size_t)T*(size_t)B*(size_t)H)
#define THB ((size_t)T*(size_t)(H*B))
#define NBLK 128
#define WSS 257        // ws row stride in float4 (bank-conflict-free padding)
#define CB16 16384u    // chunk bytes (128 k x 32 b x 4B)

typedef unsigned long long ull;

// Scratch (allocation-free: __device__ globals)
__device__ float g_pre[(size_t)T*B*G5];     // gate pre-activations
__device__ float g_hbuf[2*TBH];             // ping-pong h, layout (t,b,j) (GEMM/finalize)
__device__ float g_cbuf[2*TBH];             // ping-pong c, layout (t,b,j)
__device__ float g_hT[2*THB];               // ping-pong h, layout (t, j>>1, b, j&1) for TMA

// Two-level monotone barrier state (never reset; replay-deterministic)
__device__ unsigned g_c1[8 * 64];           // level-1 counters, 256B apart
__device__ unsigned g_c0;                   // root counter
__device__ volatile unsigned g_gen;         // generation word (read-only poll line)

__device__ __forceinline__ float sigf(float x) { return 1.0f / (1.0f + __expf(-x)); }

__device__ __forceinline__ void fma2(ull& d, ull a, ull b) {
    asm("fma.rn.f32x2 %0, %1, %2, %0;" : "+l"(d) : "l"(a), "l"(b));
}
__device__ __forceinline__ ull packdup(float x) {
    ull r; asm("mov.b64 %0, {%1, %1};" : "=l"(r) : "f"(x)); return r;
}
__device__ __forceinline__ float2 unpack2(ull v) {
    float2 f; asm("mov.b64 {%0, %1}, %2;" : "=f"(f.x), "=f"(f.y) : "l"(v)); return f;
}
__device__ __forceinline__ unsigned smem_u32(const void* p) {
    return (unsigned)__cvta_generic_to_shared(p);
}

// ---- mbarrier + bulk-copy helpers -----------------------------------------
__device__ __forceinline__ void mbar_init(unsigned a, unsigned cnt) {
    asm volatile("mbarrier.init.shared.b64 [%0], %1;" :: "r"(a), "r"(cnt) : "memory");
}
__device__ __forceinline__ void mbar_expect(unsigned a, unsigned tx) {
    asm volatile("mbarrier.arrive.expect_tx.shared.b64 _, [%0], %1;" :: "r"(a), "r"(tx) : "memory");
}
__device__ __forceinline__ void mbar_wait(unsigned a, unsigned ph) {
    unsigned done = 0;
    while (!done) {
        asm volatile(
            "{\n\t.reg .pred p;\n\t"
            "mbarrier.try_wait.parity.acquire.cta.shared::cta.b64 p, [%1], %2;\n\t"
            "selp.b32 %0, 1, 0, p;\n\t}"
            : "=r"(done) : "r"(a), "r"(ph) : "memory");
        if (!done) __nanosleep(32);
    }
}
__device__ __forceinline__ void tma_bulk(unsigned dst, const void* src, unsigned bytes, unsigned mbar) {
    asm volatile("fence.proxy.async.shared::cta;" ::: "memory");
    asm volatile(
        "cp.async.bulk.shared::cluster.global.mbarrier::complete_tx::bytes [%0], [%1], %2, [%3];"
        :: "r"(dst), "l"(src), "r"(bytes), "r"(mbar) : "memory");
}

// MAC over one 128-k chunk held as bu[kq2][b] (ull = k-pair). q = float4-k in
// chunk (0..31). Thread b-set: {2bg, 2bg+1, 2bg+16, 2bg+17}.
template<int NG>
__device__ __forceinline__ void chunk_mac(const float4* ws4, const ull* bu,
                                          ull (&acc)[NG][4], int kq4base, int kh, int jj, int bg)
{
#pragma unroll
    for (int it = 0; it < 4; it++) {
        int q = kh + it * 8;
        const ull* r = bu + (q * 64);
        ulonglong2 ha = *reinterpret_cast<const ulonglong2*>(r + 2 * bg);
        ulonglong2 hc = *reinterpret_cast<const ulonglong2*>(r + 2 * bg + 16);
        ulonglong2 hb = *reinterpret_cast<const ulonglong2*>(r + 32 + 2 * bg);
        ulonglong2 hd = *reinterpret_cast<const ulonglong2*>(r + 32 + 2 * bg + 16);
        int kqg = kq4base + q;
#pragma unroll
        for (int g = 0; g < NG; g++) {
            ulonglong2 wv = *reinterpret_cast<const ulonglong2*>(&ws4[(g * 8 + jj) * WSS + kqg]);
            fma2(acc[g][0], wv.x, ha.x); fma2(acc[g][1], wv.x, ha.y);
            fma2(acc[g][2], wv.x, hc.x); fma2(acc[g][3], wv.x, hc.y);
            fma2(acc[g][0], wv.y, hb.x); fma2(acc[g][1], wv.y, hb.y);
            fma2(acc[g][2], wv.y, hd.x); fma2(acc[g][3], wv.y, hd.y);
        }
    }
}

// ---------------------------------------------------------------------------
// GEMM: C[row(m)][n] = sum_k A[m][k] * W[n][k] + b0[n] (+ b1[n])
// ---------------------------------------------------------------------------
__global__ __launch_bounds__(256) void gemm_bias(
    const float* __restrict__ A, int lda,
    const float* __restrict__ W, int ldw,
    const float* __restrict__ b0, const float* __restrict__ b1,
    float* __restrict__ C, int ldc, int K, int swapMT)
{
    __shared__ float As[8][128];
    __shared__ float Bs[8][128];

    const int tid = threadIdx.x;
    const int m0 = blockIdx.y * 128;
    const int n0 = blockIdx.x * 128;
    const int tx = tid & 15;
    const int ty = tid >> 4;

    const int ar = tid >> 1;
    const int ac = (tid & 1) * 4;
    const float* Ap = A + (size_t)(m0 + ar) * lda + ac;
    const float* Wp = W + (size_t)(n0 + ar) * ldw + ac;

    ull acc2[8][4];
#pragma unroll
    for (int i = 0; i < 8; i++)
#pragma unroll
        for (int jp = 0; jp < 4; jp++) acc2[i][jp] = 0ULL;

    for (int k0 = 0; k0 < K; k0 += 8) {
        float4 av = *reinterpret_cast<const float4*>(Ap + k0);
        float4 wv = *reinterpret_cast<const float4*>(Wp + k0);
        __syncthreads();
        As[ac + 0][ar] = av.x; As[ac + 1][ar] = av.y;
        As[ac + 2][ar] = av.z; As[ac + 3][ar] = av.w;
        Bs[ac + 0][ar] = wv.x; Bs[ac + 1][ar] = wv.y;
        Bs[ac + 2][ar] = wv.z; Bs[ac + 3][ar] = wv.w;
        __syncthreads();
#pragma unroll
        for (int kk = 0; kk < 8; kk++) {
            const float4* arow = reinterpret_cast<const float4*>(&As[kk][ty * 8]);
            float4 alo = arow[0], ahi = arow[1];
            const ulonglong2* brow = reinterpret_cast<const ulonglong2*>(&Bs[kk][tx * 8]);
            ulonglong2 b01 = brow[0], b23 = brow[1];
            float a[8] = {alo.x, alo.y, alo.z, alo.w, ahi.x, ahi.y, ahi.z, ahi.w};
#pragma unroll
            for (int i = 0; i < 8; i++) {
                ull ad = packdup(a[i]);
                fma2(acc2[i][0], ad, b01.x);
                fma2(acc2[i][1], ad, b01.y);
                fma2(acc2[i][2], ad, b23.x);
                fma2(acc2[i][3], ad, b23.y);
            }
        }
    }

    const int nb = n0 + tx * 8;
#pragma unroll
    for (int i = 0; i < 8; i++) {
        int m = m0 + ty * 8 + i;
        int row = swapMT ? ((m & (T - 1)) * B + (m >> 8)) : m;
        float* cr = C + (size_t)row * ldc + nb;
#pragma unroll
        for (int jp = 0; jp < 4; jp++) {
            float2 v = unpack2(acc2[i][jp]);
            int n = nb + jp * 2;
            float bi0 = b0[n]     + (b1 ? b1[n]     : 0.0f);
            float bi1 = b0[n + 1] + (b1 ? b1[n + 1] : 0.0f);
            float2 o; o.x = v.x + bi0; o.y = v.y + bi1;
            *reinterpret_cast<float2*>(cr + jp * 2) = o;
        }
    }
}

// ---------------------------------------------------------------------------
// Persistent scans. smem: 128B mbar area, ws [NG*8][WSS] f4, 4x 16KB bufs.
// h staged via cp.async.bulk from g_hT, 4-deep pipeline (8 chunks).
// Two-level monotone grid barrier.
// ---------------------------------------------------------------------------
__global__ __launch_bounds__(512) void lstm0_scan(const float* __restrict__ Whh)
{
    extern __shared__ float smemf[];
    float4* ws4 = reinterpret_cast<float4*>(smemf + 32);          // [32][WSS]
    ull* bub = reinterpret_cast<ull*>(smemf + 32 + 32 * WSS * 4); // 4 x 16KB
    float* red = reinterpret_cast<float*>(bub);                   // alias

    const int tid = threadIdx.x;
    const int jbase = blockIdx.x * 8;
    const int grp8 = blockIdx.x & 7;
    const int w = tid >> 5, kh = w & 7, jj2 = w >> 3;
    const int lane = tid & 31, bg = lane & 7, jjg = lane >> 3;
    const int jj = jj2 * 4 + jjg;

    const int pj8 = tid & 7, pbb = tid >> 3;   // pointwise role (tid<256)
    const int pj = jbase + pj8;
    float creg = 0.0f;
    const unsigned mb = smem_u32(smemf);       // 4 mbarriers at mb+0,8,16,24
    const unsigned bfu = smem_u32(bub);
    unsigned ph[4] = {0, 0, 0, 0};
    unsigned gbase = 0, bar_i = 0;

    if (tid == 0) {
        gbase = g_gen;
#pragma unroll
        for (int c = 0; c < 4; c++) mbar_init(mb + c * 8, 1);
    }
    for (int i = tid; i < 32 * 256; i += 512) {
        int r = i >> 8, kq = i & 255;
        int grow = ((r >> 3) << 10) + jbase + (r & 7);
        ws4[r * WSS + kq] = *reinterpret_cast<const float4*>(Whh + (size_t)grow * H + kq * 4);
    }
    __syncthreads();

    for (int t = 0; t < T; t++) {
        float pg0 = 0, pg1 = 0, pg2 = 0, pg3 = 0;
        size_t idx = 0;
        if (tid < 256) {
            const float* xp = g_pre + ((size_t)t * B + pbb) * G4 + pj;
            pg0 = xp[0]; pg1 = xp[H]; pg2 = xp[2*H]; pg3 = xp[3*H];
            idx = ((size_t)t * B + pbb) * H + pj;
        }

        if (t > 0) {
            ull acc[4][4];
#pragma unroll
            for (int g = 0; g < 4; g++)
#pragma unroll
                for (int i = 0; i < 4; i++) acc[g][i] = 0ULL;

            const float* src = g_hT + (size_t)(t - 1) * (H * B);
            if (tid == 0) {
#pragma unroll
                for (int c = 0; c < 4; c++) {
                    mbar_expect(mb + c * 8, CB16);
                    tma_bulk(bfu + c * CB16, src + c * 4096, CB16, mb + c * 8);
                }
            }
#pragma unroll
            for (int c = 0; c < 8; c++) {
                const int bi = c & 3;
                mbar_wait(mb + bi * 8, ph[bi]); ph[bi] ^= 1;
                chunk_mac<4>(ws4, bub + bi * 2048, acc, c * 32, kh, jj, bg);
                if (c < 4) {
                    __syncthreads();
                    if (tid == 0) {
                        mbar_expect(mb + bi * 8, CB16);
                        tma_bulk(bfu + bi * CB16, src + (c + 4) * 4096, CB16, mb + bi * 8);
                    }
                }
            }
            __syncthreads();   // all buf reads done before red (aliases bufs)

#pragma unroll
            for (int g = 0; g < 4; g++)
#pragma unroll
                for (int i = 0; i < 4; i++) {
                    float2 v = unpack2(acc[g][i]);
                    red[((((kh * 2 + jj2) * 4 + g) * 4 + i) * 33) + bg * 4 + jjg] = v.x + v.y;
                }
            __syncthreads();
        }

        if (tid < 256) {
            float sg[4] = {0, 0, 0, 0};
            if (t > 0) {
                const int jj2c = pj8 >> 2, jjgc = pj8 & 3;
                const int bgc = (pbb & 15) >> 1;
                const int ic = (pbb & 1) | (((pbb >> 4) & 1) << 1);
#pragma unroll
                for (int g = 0; g < 4; g++) {
                    float s = 0.0f;
#pragma unroll
                    for (int k8 = 0; k8 < 8; k8++)
                        s += red[((((k8 * 2 + jj2c) * 4 + g) * 4 + ic) * 33) + bgc * 4 + jjgc];
                    sg[g] = s;
                }
            }
            float gi = sg[0] + pg0, gf = sg[1] + pg1, gg = sg[2] + pg2, go = sg[3] + pg3;
            float cc = sigf(gf) * creg + sigf(gi) * tanhf(gg);
            float hh = sigf(go) * tanhf(cc);
            creg = cc;
            g_hbuf[idx] = hh;
            g_cbuf[idx] = cc;
            g_hT[(size_t)t * (H * B) + (size_t)((pj >> 1) * 32 + pbb) * 2 + (pj & 1)] = hh;
        }

        if (t < T - 1) {
            __syncthreads();
            if (tid == 0) {
                __threadfence();
                unsigned v = atomicAdd(&g_c1[grp8 * 64], 1u);
                if ((v & 15u) == 15u) {
                    unsigned r = atomicAdd(&g_c0, 1u);
                    if ((r & 7u) == 7u) { __threadfence(); g_gen = g_gen + 1; }
                }
                bar_i++;
                while (g_gen - gbase < bar_i) __nanosleep(32);
                __threadfence();
            }
            __syncthreads();
        }
    }
}

__global__ __launch_bounds__(512) void ca_scan(const float* __restrict__ Wp, int src_s, int dst)
{
    extern __shared__ float smemf[];
    float4* ws4 = reinterpret_cast<float4*>(smemf + 32);          // [40][WSS]
    ull* bub = reinterpret_cast<ull*>(smemf + 32 + 40 * WSS * 4); // 4 x 16KB
    float* red = reinterpret_cast<float*>(bub);

    const int tid = threadIdx.x;
    const int jbase = blockIdx.x * 8;
    const int grp8 = blockIdx.x & 7;
    const int w = tid >> 5, kh = w & 7, jj2 = w >> 3;
    const int lane = tid & 31, bg = lane & 7, jjg = lane >> 3;
    const int jj = jj2 * 4 + jjg;

    const int pj8 = tid & 7, pbb = tid >> 3;
    const int pj = jbase + pj8;
    float creg = 0.0f;
    const unsigned mb = smem_u32(smemf);
    const unsigned bfu = smem_u32(bub);
    unsigned ph[4] = {0, 0, 0, 0};
    unsigned gbase = 0, bar_i = 0;

    if (tid == 0) {
        gbase = g_gen;
#pragma unroll
        for (int c = 0; c < 4; c++) mbar_init(mb + c * 8, 1);
    }
    for (int i = tid; i < 40 * 256; i += 512) {
        int r = i >> 8, kq = i & 255;
        int grow = (r >> 3) * H + jbase + (r & 7);
        ws4[r * WSS + kq] = *reinterpret_cast<const float4*>(Wp + (size_t)grow * (2 * H) + kq * 4);
    }
    __syncthreads();

    for (int t = 0; t < T; t++) {
        float pg0 = 0, pg1 = 0, pg2 = 0, pg3 = 0, pg4 = 0, cl = 0;
        size_t idx = 0;
        if (tid < 256) {
            const float* pre = g_pre + ((size_t)t * B + pbb) * G5 + pj;
            pg0 = pre[0]; pg1 = pre[H]; pg2 = pre[2*H]; pg3 = pre[3*H]; pg4 = pre[4*H];
            idx = ((size_t)t * B + pbb) * H + pj;
            cl = g_cbuf[(size_t)src_s * TBH + idx];
        }

        if (t > 0) {
            ull acc[5][4];
#pragma unroll
            for (int g = 0; g < 5; g++)
#pragma unroll
                for (int i = 0; i < 4; i++) acc[g][i] = 0ULL;

            const float* src = g_hT + (size_t)dst * THB + (size_t)(t - 1) * (H * B);
            if (tid == 0) {
#pragma unroll
                for (int c = 0; c < 4; c++) {
                    mbar_expect(mb + c * 8, CB16);
                    tma_bulk(bfu + c * CB16, src + c * 4096, CB16, mb + c * 8);
                }
            }
#pragma unroll
            for (int c = 0; c < 8; c++) {
                const int bi = c & 3;
                mbar_wait(mb + bi * 8, ph[bi]); ph[bi] ^= 1;
                chunk_mac<5>(ws4, bub + bi * 2048, acc, c * 32, kh, jj, bg);
                if (c < 4) {
                    __syncthreads();
                    if (tid == 0) {
                        mbar_expect(mb + bi * 8, CB16);
                        tma_bulk(bfu + bi * CB16, src + (c + 4) * 4096, CB16, mb + bi * 8);
                    }
                }
            }
            __syncthreads();

#pragma unroll
            for (int g = 0; g < 5; g++)
#pragma unroll
                for (int i = 0; i < 4; i++) {
                    float2 v = unpack2(acc[g][i]);
                    red[((((kh * 2 + jj2) * 5 + g) * 4 + i) * 33) + bg * 4 + jjg] = v.x + v.y;
                }
            __syncthreads();
        }

        if (tid < 256) {
            float sg[5] = {0, 0, 0, 0, 0};
            if (t > 0) {
                const int jj2c = pj8 >> 2, jjgc = pj8 & 3;
                const int bgc = (pbb & 15) >> 1;
                const int ic = (pbb & 1) | (((pbb >> 4) & 1) << 1);
#pragma unroll
                for (int g = 0; g < 5; g++) {
                    float s = 0.0f;
#pragma unroll
                    for (int k8 = 0; k8 < 8; k8++)
                        s += red[((((k8 * 2 + jj2c) * 5 + g) * 4 + ic) * 33) + bgc * 4 + jjgc];
                    sg[g] = s;
                }
            }
            float gi  = sg[0] + pg0;
            float gfp = sg[1] + pg1;
            float gfl = sg[2] + pg2;
            float gu  = sg[3] + pg3;
            float go  = sg[4] + pg4;
            float cc = creg * sigf(gfp + 1.0f) + cl * sigf(gfl + 1.0f) + tanhf(gu) * sigf(gi);
            float hh = sigf(go) * tanhf(cc);
            creg = cc;
            g_hbuf[(size_t)dst * TBH + idx] = hh;
            g_cbuf[(size_t)dst * TBH + idx] = cc;
            g_hT[(size_t)dst * THB + (size_t)t * (H * B) + (size_t)((pj >> 1) * 32 + pbb) * 2 + (pj & 1)] = hh;
        }

        if (t < T - 1) {
            __syncthreads();
            if (tid == 0) {
                __threadfence();
                unsigned v = atomicAdd(&g_c1[grp8 * 64], 1u);
                if ((v & 15u) == 15u) {
                    unsigned r = atomicAdd(&g_c0, 1u);
                    if ((r & 7u) == 7u) { __threadfence(); g_gen = g_gen + 1; }
                }
                bar_i++;
                while (g_gen - gbase < bar_i) __nanosleep(32);
                __threadfence();
            }
            __syncthreads();
        }
    }
}

// ---------------------------------------------------------------------------
// Final transpose (t,b,j) -> (b,t,j); h then c into d_out.
// ---------------------------------------------------------------------------
__global__ __launch_bounds__(256) void finalize(int fin, float* __restrict__ out)
{
    size_t gid = (size_t)blockIdx.x * 256 + threadIdx.x;
    int j = (int)(gid & (H - 1));
    int bt = (int)(gid >> 10);
    int t = bt & (T - 1);
    int b = bt >> 8;
    size_t srci = ((size_t)t * B + b) * H + j;
    out[gid]       = g_hbuf[(size_t)fin * TBH + srci];
    out[TBH + gid] = g_cbuf[(size_t)fin * TBH + srci];
}

// ---------------------------------------------------------------------------
extern "C" void kernel_launch(void* const* d_in, const int* in_sizes, int n_in,
                              void* d_out, int out_size)
{
    (void)in_sizes; (void)n_in; (void)out_size;
    const float* inputs = (const float*)d_in[0];
    const float* W_ih0  = (const float*)d_in[1];
    const float* W_hh0  = (const float*)d_in[2];
    const float* b_ih0  = (const float*)d_in[3];
    const float* b_hh0  = (const float*)d_in[4];
    const float* W_ca   = (const float*)d_in[5];
    const float* b_ca   = (const float*)d_in[6];
    float* out = (float*)d_out;

    float* pre = nullptr;
    float* hb  = nullptr;
    cudaGetSymbolAddress((void**)&pre, g_pre);
    cudaGetSymbolAddress((void**)&hb,  g_hbuf);

    const int smem0 = (32 + 32 * WSS * 4) * 4 + 4 * (int)CB16;   // 197,248
    const int smemC = (32 + 40 * WSS * 4) * 4 + 4 * (int)CB16;   // 230,144
    cudaFuncSetAttribute(lstm0_scan, cudaFuncAttributeMaxDynamicSharedMemorySize, smem0);
    cudaFuncSetAttribute(ca_scan,    cudaFuncAttributeMaxDynamicSharedMemorySize, smemC);

    gemm_bias<<<dim3(G4 / 128, (B * T) / 128), 256>>>(
        inputs, DI, W_ih0, DI, b_ih0, b_hh0, pre, G4, DI, 1);
    lstm0_scan<<<NBLK, 512, smem0>>>(W_hh0);

    int src = 0;
    for (int l = 0; l < 3; l++) {
        int dst = 1 - src;
        gemm_bias<<<dim3(G5 / 128, (B * T) / 128), 256>>>(
            hb + (size_t)src * TBH, H,
            W_ca + (size_t)l * G5 * (2 * H), 2 * H,
            b_ca + (size_t)l * G5, nullptr,
            pre, G5, H, 0);
        ca_scan<<<NBLK, 512, smemC>>>(W_ca + (size_t)l * G5 * (2 * H) + H, src, dst);
        src = dst;
    }

    finalize<<<(int)(TBH / 256), 256>>>(src, out);
}

// round 16
// speedup vs baseline: 1.6122x; 1.2766x over previous
#include <cuda_runtime.h>
#include <cuda_bf16.h>
#include <cstdint>
#include <math.h>

#define B 32
#define T 256
#define DI 512
#define H 1024
#define G4 (4*H)
#define G5 (5*H)
#define TBH ((size_t)T*(size_t)B*(size_t)H)
#define THB ((size_t)T*(size_t)(H*B))
#define NBLK 128
#define WSS 257        // scan ws row stride in float4
#define CB16 16384u    // scan chunk bytes

typedef unsigned long long ull;

// Scratch (allocation-free: __device__ globals)
__device__ float g_pre[(size_t)T*B*G5];
__device__ float g_hbuf[2*TBH];
__device__ float g_cbuf[2*TBH];
__device__ float g_hT[2*THB];

// bf16-split pre-tiled planes for tensor GEMMs
__device__ __align__(128) __nv_bfloat16 g_xbh[(size_t)B*T*DI], g_xbl[(size_t)B*T*DI];
__device__ __align__(128) __nv_bfloat16 g_hbh[(size_t)B*T*H],  g_hbl[(size_t)B*T*H];
__device__ __align__(128) __nv_bfloat16 g_w0h[(size_t)G4*DI],  g_w0l[(size_t)G4*DI];
__device__ __align__(128) __nv_bfloat16 g_wch[(size_t)3*G5*H], g_wcl[(size_t)3*G5*H];

// Two-level monotone barrier state (never reset; replay-deterministic)
__device__ unsigned g_c1[8 * 64];
__device__ unsigned g_c0;
__device__ volatile unsigned g_gen;

__device__ __forceinline__ float sigf(float x) { return 1.0f / (1.0f + __expf(-x)); }

__device__ __forceinline__ void fma2(ull& d, ull a, ull b) {
    asm("fma.rn.f32x2 %0, %1, %2, %0;" : "+l"(d) : "l"(a), "l"(b));
}
__device__ __forceinline__ float2 unpack2(ull v) {
    float2 f; asm("mov.b64 {%0, %1}, %2;" : "=f"(f.x), "=f"(f.y) : "l"(v)); return f;
}
__device__ __forceinline__ unsigned smem_u32(const void* p) {
    return (unsigned)__cvta_generic_to_shared(p);
}

// ---- mbarrier / bulk-copy helpers ------------------------------------------
__device__ __forceinline__ void mbar_init(unsigned a, unsigned cnt) {
    asm volatile("mbarrier.init.shared.b64 [%0], %1;" :: "r"(a), "r"(cnt) : "memory");
}
__device__ __forceinline__ void mbar_expect(unsigned a, unsigned tx) {
    asm volatile("mbarrier.arrive.expect_tx.shared.b64 _, [%0], %1;" :: "r"(a), "r"(tx) : "memory");
}
__device__ __forceinline__ void mbar_wait(unsigned a, unsigned ph) {
    unsigned done = 0;
    while (!done) {
        asm volatile(
            "{\n\t.reg .pred p;\n\t"
            "mbarrier.try_wait.parity.acquire.cta.shared::cta.b64 p, [%1], %2;\n\t"
            "selp.b32 %0, 1, 0, p;\n\t}"
            : "=r"(done) : "r"(a), "r"(ph) : "memory");
        if (!done) __nanosleep(32);
    }
}
__device__ __forceinline__ void tma_bulk(unsigned dst, const void* src, unsigned bytes, unsigned mbar) {
    asm volatile("fence.proxy.async.shared::cta;" ::: "memory");
    asm volatile(
        "cp.async.bulk.shared::cluster.global.mbarrier::complete_tx::bytes [%0], [%1], %2, [%3];"
        :: "r"(dst), "l"(src), "r"(bytes), "r"(mbar) : "memory");
}

// ---- warp MMA helpers (sm_80+ PTX; legal on plain sm_103 target) ------------
__device__ __forceinline__ void ldsm4(unsigned* r, unsigned addr) {
    asm volatile("ldmatrix.sync.aligned.m8n8.x4.shared.b16 {%0,%1,%2,%3}, [%4];"
                 : "=r"(r[0]), "=r"(r[1]), "=r"(r[2]), "=r"(r[3]) : "r"(addr));
}
__device__ __forceinline__ void mma16816(float* d, const unsigned* a, const unsigned* b) {
    asm volatile(
        "mma.sync.aligned.m16n8k16.row.col.f32.bf16.bf16.f32 "
        "{%0,%1,%2,%3}, {%4,%5,%6,%7}, {%8,%9}, {%0,%1,%2,%3};"
        : "+f"(d[0]), "+f"(d[1]), "+f"(d[2]), "+f"(d[3])
        : "r"(a[0]), "r"(a[1]), "r"(a[2]), "r"(a[3]), "r"(b[0]), "r"(b[1]));
}

static __device__ __forceinline__ unsigned SWZ(unsigned off) { return off ^ ((off >> 3) & 0x70); }

// ---------------------------------------------------------------------------
// conv_pack: fp32 [R][ld] -> bf16 hi/lo planes, pre-tiled + SW128-swizzled.
// Tile = (1<<logRT) rows x 64 k (row byte-pitch 128). logRT: 7 for A, 6 for B.
// ---------------------------------------------------------------------------
__global__ __launch_bounds__(256) void conv_pack(
    const float* __restrict__ src, int ld, int logK, int logRT,
    __nv_bfloat16* __restrict__ hi, __nv_bfloat16* __restrict__ lo)
{
    size_t i = (size_t)blockIdx.x * 256 + threadIdx.x;
    int K = 1 << logK;
    size_t r = i >> logK;
    int k = (int)(i & (size_t)(K - 1));
    float v = src[r * (size_t)ld + k];
    int rb = (int)(r >> logRT);
    int rl = (int)(r & ((1 << logRT) - 1));
    int kc = k >> 6, kl = k & 63;
    unsigned off = SWZ((unsigned)(rl * 128 + kl * 2)) >> 1;
    size_t tile = ((size_t)rb * (K >> 6) + kc) * ((size_t)(1 << logRT) * 64);
    __nv_bfloat16 h = __float2bfloat16(v);
    hi[tile + off] = h;
    lo[tile + off] = __float2bfloat16(v - __bfloat162float(h));
}

// ---------------------------------------------------------------------------
// Warp-MMA GEMM (bf16x2 split, 3 passes): C[m][n] = A[m][:] . W[n][:] + bias
// Block tile 128m x 64n; K chunks of 64 staged via cp.async.bulk (pre-tiled
// gmem), double-buffered. 8 warps = 2m x 4n, each 64m x 16n.
// ---------------------------------------------------------------------------
#define ATILE 8192
#define BTILE 4096
#define CHB 49152u
#define GSH 1024
#define GEMM_SMEM (GSH + 2*49152)

__global__ __launch_bounds__(256, 2) void gemm_mma(
    const __nv_bfloat16* __restrict__ Ah, const __nv_bfloat16* __restrict__ Al,
    const __nv_bfloat16* __restrict__ Bh, const __nv_bfloat16* __restrict__ Bl,
    const float* __restrict__ b0, const float* __restrict__ b1,
    float* __restrict__ C, int ldc, int nkc, int swapMT)
{
    extern __shared__ char smem[];
    const unsigned sb = smem_u32(smem);
    const int tid = threadIdx.x;
    const int lane = tid & 31, wid = tid >> 5;
    const int wm = wid >> 2, wn = wid & 3;
    const int nb = blockIdx.x, mb = blockIdx.y;
    const int n0 = nb * 64, m0 = mb * 128;

    if (tid < 64) {
        float bias = b0[n0 + tid] + (b1 ? b1[n0 + tid] : 0.0f);
        reinterpret_cast<float*>(smem + 64)[tid] = bias;
    }
    if (tid == 0) { mbar_init(sb + 0, 1); mbar_init(sb + 8, 1); }
    __syncthreads();

    const __nv_bfloat16* tAh = Ah + (size_t)mb * nkc * ATILE;
    const __nv_bfloat16* tAl = Al + (size_t)mb * nkc * ATILE;
    const __nv_bfloat16* tBh = Bh + (size_t)nb * nkc * BTILE;
    const __nv_bfloat16* tBl = Bl + (size_t)nb * nkc * BTILE;

    if (tid == 0) {
        mbar_expect(sb, CHB);
        tma_bulk(sb + GSH,         tAh, 16384, sb);
        tma_bulk(sb + GSH + 16384, tAl, 16384, sb);
        tma_bulk(sb + GSH + 32768, tBh, 8192,  sb);
        tma_bulk(sb + GSH + 40960, tBl, 8192,  sb);
    }

    // lane-constant ldmatrix address pieces
    const unsigned axor = (unsigned)(lane & 7) * 16;
    const unsigned ahalf = (unsigned)(lane >> 4) * 16;        // A: k-half select
    const int mi = lane >> 3;
    const unsigned bhalf = (unsigned)(mi & 1) * 16;           // B: k-half select
    const int brow = wn * 16 + (lane & 7) + (mi >> 1) * 8;    // B: n-row
    unsigned aBase[4];
#pragma unroll
    for (int i = 0; i < 4; i++)
        aBase[i] = (unsigned)((wm * 64 + i * 16 + (lane & 15)) * 128);
    const unsigned bBase = (unsigned)(brow * 128);

    float d[4][2][4];
#pragma unroll
    for (int i = 0; i < 4; i++)
#pragma unroll
        for (int j = 0; j < 2; j++)
#pragma unroll
            for (int q = 0; q < 4; q++) d[i][j][q] = 0.0f;

    unsigned ph[2] = {0, 0};
    int cur = 0;
    for (int kci = 0; kci < nkc; kci++) {
        mbar_wait(sb + cur * 8, ph[cur]); ph[cur] ^= 1;
        __syncthreads();
        if (tid == 0 && kci + 1 < nkc) {
            int nx = cur ^ 1;
            unsigned db = sb + GSH + nx * 49152;
            mbar_expect(sb + nx * 8, CHB);
            tma_bulk(db,         tAh + (size_t)(kci + 1) * ATILE, 16384, sb + nx * 8);
            tma_bulk(db + 16384, tAl + (size_t)(kci + 1) * ATILE, 16384, sb + nx * 8);
            tma_bulk(db + 32768, tBh + (size_t)(kci + 1) * BTILE, 8192,  sb + nx * 8);
            tma_bulk(db + 40960, tBl + (size_t)(kci + 1) * BTILE, 8192,  sb + nx * 8);
        }
        const unsigned bAh = sb + GSH + cur * 49152;
        const unsigned bAl = bAh + 16384;
        const unsigned bBh = bAh + 32768;
        const unsigned bBl = bAh + 40960;
#pragma unroll
        for (int ks = 0; ks < 4; ks++) {
            const unsigned aoff = ((unsigned)ks * 32 + ahalf) ^ axor;
            const unsigned boff = ((unsigned)ks * 32 + bhalf) ^ axor;
            unsigned ah[4][4], al[4][4], bh[4], bl[4];
            ldsm4(bh, bBh + bBase + boff);
            ldsm4(bl, bBl + bBase + boff);
#pragma unroll
            for (int i = 0; i < 4; i++) {
                ldsm4(ah[i], bAh + aBase[i] + aoff);
                ldsm4(al[i], bAl + aBase[i] + aoff);
            }
#pragma unroll
            for (int i = 0; i < 4; i++)
#pragma unroll
                for (int j = 0; j < 2; j++) {
                    mma16816(d[i][j], ah[i], bh + j * 2);
                    mma16816(d[i][j], ah[i], bl + j * 2);
                    mma16816(d[i][j], al[i], bh + j * 2);
                }
        }
        cur ^= 1;
    }

    // epilogue
    const float* bias = reinterpret_cast<const float*>(smem + 64);
    const int gid = lane >> 2, tig = lane & 3;
#pragma unroll
    for (int i = 0; i < 4; i++) {
        int mA = m0 + wm * 64 + i * 16 + gid;
        int mB = mA + 8;
        int rowA = swapMT ? ((mA & 255) * 32 + (mA >> 8)) : mA;
        int rowB = swapMT ? ((mB & 255) * 32 + (mB >> 8)) : mB;
#pragma unroll
        for (int j = 0; j < 2; j++) {
            int nl = wn * 16 + j * 8 + tig * 2;
            float2 vA; vA.x = d[i][j][0] + bias[nl]; vA.y = d[i][j][1] + bias[nl + 1];
            float2 vB; vB.x = d[i][j][2] + bias[nl]; vB.y = d[i][j][3] + bias[nl + 1];
            *reinterpret_cast<float2*>(C + (size_t)rowA * ldc + n0 + nl) = vA;
            *reinterpret_cast<float2*>(C + (size_t)rowB * ldc + n0 + nl) = vB;
        }
    }
}

// ---------------------------------------------------------------------------
// Persistent scans (byte-identical to R14 best).
// ---------------------------------------------------------------------------
template<int NG>
__device__ __forceinline__ void chunk_mac(const float4* ws4, const ull* bu,
                                          ull (&acc)[NG][4], int kq4base, int kh, int jj, int bg)
{
#pragma unroll
    for (int it = 0; it < 4; it++) {
        int q = kh + it * 8;
        const ull* r = bu + (q * 64);
        ulonglong2 ha = *reinterpret_cast<const ulonglong2*>(r + 2 * bg);
        ulonglong2 hc = *reinterpret_cast<const ulonglong2*>(r + 2 * bg + 16);
        ulonglong2 hb = *reinterpret_cast<const ulonglong2*>(r + 32 + 2 * bg);
        ulonglong2 hd = *reinterpret_cast<const ulonglong2*>(r + 32 + 2 * bg + 16);
        int kqg = kq4base + q;
#pragma unroll
        for (int g = 0; g < NG; g++) {
            ulonglong2 wv = *reinterpret_cast<const ulonglong2*>(&ws4[(g * 8 + jj) * WSS + kqg]);
            fma2(acc[g][0], wv.x, ha.x); fma2(acc[g][1], wv.x, ha.y);
            fma2(acc[g][2], wv.x, hc.x); fma2(acc[g][3], wv.x, hc.y);
            fma2(acc[g][0], wv.y, hb.x); fma2(acc[g][1], wv.y, hb.y);
            fma2(acc[g][2], wv.y, hd.x); fma2(acc[g][3], wv.y, hd.y);
        }
    }
}

__global__ __launch_bounds__(512) void lstm0_scan(const float* __restrict__ Whh)
{
    extern __shared__ float smemf[];
    float4* ws4 = reinterpret_cast<float4*>(smemf + 32);
    ull* bub = reinterpret_cast<ull*>(smemf + 32 + 32 * WSS * 4);
    float* red = reinterpret_cast<float*>(bub);

    const int tid = threadIdx.x;
    const int jbase = blockIdx.x * 8;
    const int grp8 = blockIdx.x & 7;
    const int w = tid >> 5, kh = w & 7, jj2 = w >> 3;
    const int lane = tid & 31, bg = lane & 7, jjg = lane >> 3;
    const int jj = jj2 * 4 + jjg;

    const int pj8 = tid & 7, pbb = tid >> 3;
    const int pj = jbase + pj8;
    float creg = 0.0f;
    const unsigned mb = smem_u32(smemf);
    const unsigned bfu = smem_u32(bub);
    unsigned ph[4] = {0, 0, 0, 0};
    unsigned gbase = 0, bar_i = 0;

    if (tid == 0) {
        gbase = g_gen;
#pragma unroll
        for (int c = 0; c < 4; c++) mbar_init(mb + c * 8, 1);
    }
    for (int i = tid; i < 32 * 256; i += 512) {
        int r = i >> 8, kq = i & 255;
        int grow = ((r >> 3) << 10) + jbase + (r & 7);
        ws4[r * WSS + kq] = *reinterpret_cast<const float4*>(Whh + (size_t)grow * H + kq * 4);
    }
    __syncthreads();

    for (int t = 0; t < T; t++) {
        float pg0 = 0, pg1 = 0, pg2 = 0, pg3 = 0;
        size_t idx = 0;
        if (tid < 256) {
            const float* xp = g_pre + ((size_t)t * B + pbb) * G4 + pj;
            pg0 = xp[0]; pg1 = xp[H]; pg2 = xp[2*H]; pg3 = xp[3*H];
            idx = ((size_t)t * B + pbb) * H + pj;
        }

        if (t > 0) {
            ull acc[4][4];
#pragma unroll
            for (int g = 0; g < 4; g++)
#pragma unroll
                for (int i = 0; i < 4; i++) acc[g][i] = 0ULL;

            const float* src = g_hT + (size_t)(t - 1) * (H * B);
            if (tid == 0) {
#pragma unroll
                for (int c = 0; c < 4; c++) {
                    mbar_expect(mb + c * 8, CB16);
                    tma_bulk(bfu + c * CB16, src + c * 4096, CB16, mb + c * 8);
                }
            }
#pragma unroll
            for (int c = 0; c < 8; c++) {
                const int bi = c & 3;
                mbar_wait(mb + bi * 8, ph[bi]); ph[bi] ^= 1;
                chunk_mac<4>(ws4, bub + bi * 2048, acc, c * 32, kh, jj, bg);
                if (c < 4) {
                    __syncthreads();
                    if (tid == 0) {
                        mbar_expect(mb + bi * 8, CB16);
                        tma_bulk(bfu + bi * CB16, src + (c + 4) * 4096, CB16, mb + bi * 8);
                    }
                }
            }
            __syncthreads();

#pragma unroll
            for (int g = 0; g < 4; g++)
#pragma unroll
                for (int i = 0; i < 4; i++) {
                    float2 v = unpack2(acc[g][i]);
                    red[((((kh * 2 + jj2) * 4 + g) * 4 + i) * 33) + bg * 4 + jjg] = v.x + v.y;
                }
            __syncthreads();
        }

        if (tid < 256) {
            float sg[4] = {0, 0, 0, 0};
            if (t > 0) {
                const int jj2c = pj8 >> 2, jjgc = pj8 & 3;
                const int bgc = (pbb & 15) >> 1;
                const int ic = (pbb & 1) | (((pbb >> 4) & 1) << 1);
#pragma unroll
                for (int g = 0; g < 4; g++) {
                    float s = 0.0f;
#pragma unroll
                    for (int k8 = 0; k8 < 8; k8++)
                        s += red[((((k8 * 2 + jj2c) * 4 + g) * 4 + ic) * 33) + bgc * 4 + jjgc];
                    sg[g] = s;
                }
            }
            float gi = sg[0] + pg0, gf = sg[1] + pg1, gg = sg[2] + pg2, go = sg[3] + pg3;
            float cc = sigf(gf) * creg + sigf(gi) * tanhf(gg);
            float hh = sigf(go) * tanhf(cc);
            creg = cc;
            g_hbuf[idx] = hh;
            g_cbuf[idx] = cc;
            g_hT[(size_t)t * (H * B) + (size_t)((pj >> 1) * 32 + pbb) * 2 + (pj & 1)] = hh;
        }

        if (t < T - 1) {
            __syncthreads();
            if (tid == 0) {
                __threadfence();
                unsigned v = atomicAdd(&g_c1[grp8 * 64], 1u);
                if ((v & 15u) == 15u) {
                    unsigned r = atomicAdd(&g_c0, 1u);
                    if ((r & 7u) == 7u) { __threadfence(); g_gen = g_gen + 1; }
                }
                bar_i++;
                while (g_gen - gbase < bar_i) __nanosleep(32);
                __threadfence();
            }
            __syncthreads();
        }
    }
}

__global__ __launch_bounds__(512) void ca_scan(const float* __restrict__ Wp, int src_s, int dst)
{
    extern __shared__ float smemf[];
    float4* ws4 = reinterpret_cast<float4*>(smemf + 32);
    ull* bub = reinterpret_cast<ull*>(smemf + 32 + 40 * WSS * 4);
    float* red = reinterpret_cast<float*>(bub);

    const int tid = threadIdx.x;
    const int jbase = blockIdx.x * 8;
    const int grp8 = blockIdx.x & 7;
    const int w = tid >> 5, kh = w & 7, jj2 = w >> 3;
    const int lane = tid & 31, bg = lane & 7, jjg = lane >> 3;
    const int jj = jj2 * 4 + jjg;

    const int pj8 = tid & 7, pbb = tid >> 3;
    const int pj = jbase + pj8;
    float creg = 0.0f;
    const unsigned mb = smem_u32(smemf);
    const unsigned bfu = smem_u32(bub);
    unsigned ph[4] = {0, 0, 0, 0};
    unsigned gbase = 0, bar_i = 0;

    if (tid == 0) {
        gbase = g_gen;
#pragma unroll
        for (int c = 0; c < 4; c++) mbar_init(mb + c * 8, 1);
    }
    for (int i = tid; i < 40 * 256; i += 512) {
        int r = i >> 8, kq = i & 255;
        int grow = (r >> 3) * H + jbase + (r & 7);
        ws4[r * WSS + kq] = *reinterpret_cast<const float4*>(Wp + (size_t)grow * (2 * H) + kq * 4);
    }
    __syncthreads();

    for (int t = 0; t < T; t++) {
        float pg0 = 0, pg1 = 0, pg2 = 0, pg3 = 0, pg4 = 0, cl = 0;
        size_t idx = 0;
        if (tid < 256) {
            const float* pre = g_pre + ((size_t)t * B + pbb) * G5 + pj;
            pg0 = pre[0]; pg1 = pre[H]; pg2 = pre[2*H]; pg3 = pre[3*H]; pg4 = pre[4*H];
            idx = ((size_t)t * B + pbb) * H + pj;
            cl = g_cbuf[(size_t)src_s * TBH + idx];
        }

        if (t > 0) {
            ull acc[5][4];
#pragma unroll
            for (int g = 0; g < 5; g++)
#pragma unroll
                for (int i = 0; i < 4; i++) acc[g][i] = 0ULL;

            const float* src = g_hT + (size_t)dst * THB + (size_t)(t - 1) * (H * B);
            if (tid == 0) {
#pragma unroll
                for (int c = 0; c < 4; c++) {
                    mbar_expect(mb + c * 8, CB16);
                    tma_bulk(bfu + c * CB16, src + c * 4096, CB16, mb + c * 8);
                }
            }
#pragma unroll
            for (int c = 0; c < 8; c++) {
                const int bi = c & 3;
                mbar_wait(mb + bi * 8, ph[bi]); ph[bi] ^= 1;
                chunk_mac<5>(ws4, bub + bi * 2048, acc, c * 32, kh, jj, bg);
                if (c < 4) {
                    __syncthreads();
                    if (tid == 0) {
                        mbar_expect(mb + bi * 8, CB16);
                        tma_bulk(bfu + bi * CB16, src + (c + 4) * 4096, CB16, mb + bi * 8);
                    }
                }
            }
            __syncthreads();

#pragma unroll
            for (int g = 0; g < 5; g++)
#pragma unroll
                for (int i = 0; i < 4; i++) {
                    float2 v = unpack2(acc[g][i]);
                    red[((((kh * 2 + jj2) * 5 + g) * 4 + i) * 33) + bg * 4 + jjg] = v.x + v.y;
                }
            __syncthreads();
        }

        if (tid < 256) {
            float sg[5] = {0, 0, 0, 0, 0};
            if (t > 0) {
                const int jj2c = pj8 >> 2, jjgc = pj8 & 3;
                const int bgc = (pbb & 15) >> 1;
                const int ic = (pbb & 1) | (((pbb >> 4) & 1) << 1);
#pragma unroll
                for (int g = 0; g < 5; g++) {
                    float s = 0.0f;
#pragma unroll
                    for (int k8 = 0; k8 < 8; k8++)
                        s += red[((((k8 * 2 + jj2c) * 5 + g) * 4 + ic) * 33) + bgc * 4 + jjgc];
                    sg[g] = s;
                }
            }
            float gi  = sg[0] + pg0;
            float gfp = sg[1] + pg1;
            float gfl = sg[2] + pg2;
            float gu  = sg[3] + pg3;
            float go  = sg[4] + pg4;
            float cc = creg * sigf(gfp + 1.0f) + cl * sigf(gfl + 1.0f) + tanhf(gu) * sigf(gi);
            float hh = sigf(go) * tanhf(cc);
            creg = cc;
            g_hbuf[(size_t)dst * TBH + idx] = hh;
            g_cbuf[(size_t)dst * TBH + idx] = cc;
            g_hT[(size_t)dst * THB + (size_t)t * (H * B) + (size_t)((pj >> 1) * 32 + pbb) * 2 + (pj & 1)] = hh;
        }

        if (t < T - 1) {
            __syncthreads();
            if (tid == 0) {
                __threadfence();
                unsigned v = atomicAdd(&g_c1[grp8 * 64], 1u);
                if ((v & 15u) == 15u) {
                    unsigned r = atomicAdd(&g_c0, 1u);
                    if ((r & 7u) == 7u) { __threadfence(); g_gen = g_gen + 1; }
                }
                bar_i++;
                while (g_gen - gbase < bar_i) __nanosleep(32);
                __threadfence();
            }
            __syncthreads();
        }
    }
}

// ---------------------------------------------------------------------------
__global__ __launch_bounds__(256) void finalize(int fin, float* __restrict__ out)
{
    size_t gid = (size_t)blockIdx.x * 256 + threadIdx.x;
    int j = (int)(gid & (H - 1));
    int bt = (int)(gid >> 10);
    int t = bt & (T - 1);
    int b = bt >> 8;
    size_t srci = ((size_t)t * B + b) * H + j;
    out[gid]       = g_hbuf[(size_t)fin * TBH + srci];
    out[TBH + gid] = g_cbuf[(size_t)fin * TBH + srci];
}

// ---------------------------------------------------------------------------
extern "C" void kernel_launch(void* const* d_in, const int* in_sizes, int n_in,
                              void* d_out, int out_size)
{
    (void)in_sizes; (void)n_in; (void)out_size;
    const float* inputs = (const float*)d_in[0];
    const float* W_ih0  = (const float*)d_in[1];
    const float* W_hh0  = (const float*)d_in[2];
    const float* b_ih0  = (const float*)d_in[3];
    const float* b_hh0  = (const float*)d_in[4];
    const float* W_ca   = (const float*)d_in[5];
    const float* b_ca   = (const float*)d_in[6];
    float* out = (float*)d_out;

    float* pre = nullptr;
    float* hb  = nullptr;
    cudaGetSymbolAddress((void**)&pre, g_pre);
    cudaGetSymbolAddress((void**)&hb,  g_hbuf);
    __nv_bfloat16 *xbh, *xbl, *hbh, *hbl, *w0h, *w0l, *wch, *wcl;
    cudaGetSymbolAddress((void**)&xbh, g_xbh);  cudaGetSymbolAddress((void**)&xbl, g_xbl);
    cudaGetSymbolAddress((void**)&hbh, g_hbh);  cudaGetSymbolAddress((void**)&hbl, g_hbl);
    cudaGetSymbolAddress((void**)&w0h, g_w0h);  cudaGetSymbolAddress((void**)&w0l, g_w0l);
    cudaGetSymbolAddress((void**)&wch, g_wch);  cudaGetSymbolAddress((void**)&wcl, g_wcl);

    const int smem0 = (32 + 32 * WSS * 4) * 4 + 4 * (int)CB16;
    const int smemC = (32 + 40 * WSS * 4) * 4 + 4 * (int)CB16;
    cudaFuncSetAttribute(lstm0_scan, cudaFuncAttributeMaxDynamicSharedMemorySize, smem0);
    cudaFuncSetAttribute(ca_scan,    cudaFuncAttributeMaxDynamicSharedMemorySize, smemC);
    cudaFuncSetAttribute(gemm_mma,   cudaFuncAttributeMaxDynamicSharedMemorySize, GEMM_SMEM);

    // pack inputs + weights (bf16 split, tiled+swizzled)
    conv_pack<<<(B * T * DI) / 256, 256>>>(inputs, DI, 9, 7, xbh, xbl);
    conv_pack<<<(G4 * DI) / 256, 256>>>(W_ih0, DI, 9, 6, w0h, w0l);
    for (int l = 0; l < 3; l++)
        conv_pack<<<(G5 * H) / 256, 256>>>(W_ca + (size_t)l * G5 * (2 * H), 2 * H, 10, 6,
                                           wch + (size_t)l * G5 * H, wcl + (size_t)l * G5 * H);

    // Layer 0 pre-GEMM (warp MMA)
    gemm_mma<<<dim3(G4 / 64, (B * T) / 128), 256, GEMM_SMEM>>>(
        xbh, xbl, w0h, w0l, b_ih0, b_hh0, pre, G4, DI / 64, 1);
    lstm0_scan<<<NBLK, 512, smem0>>>(W_hh0);

    int src = 0;
    for (int l = 0; l < 3; l++) {
        int dst = 1 - src;
        conv_pack<<<(B * T * H) / 256, 256>>>(hb + (size_t)src * TBH, H, 10, 7, hbh, hbl);
        gemm_mma<<<dim3(G5 / 64, (B * T) / 128), 256, GEMM_SMEM>>>(
            hbh, hbl, wch + (size_t)l * G5 * H, wcl + (size_t)l * G5 * H,
            b_ca + (size_t)l * G5, nullptr, pre, G5, H / 64, 0);
        ca_scan<<<NBLK, 512, smemC>>>(W_ca + (size_t)l * G5 * (2 * H) + H, src, dst);
        src = dst;
    }

    finalize<<<(int)(TBH / 256), 256>>>(src, out);
}

// round 17
// speedup vs baseline: 2.5178x; 1.5618x over previous
#include <cuda_runtime.h>
#include <cuda_bf16.h>
#include <cstdint>
#include <math.h>

#define B 32
#define T 256
#define DI 512
#define H 1024
#define G4 (4*H)
#define G5 (5*H)
#define TBH ((size_t)T*(size_t)B*(size_t)H)
#define NBLK 128

typedef unsigned long long ull;
typedef __nv_bfloat16 bf16;

// Scratch (allocation-free: __device__ globals)
__device__ float g_pre[(size_t)T*B*G5];
__device__ float g_hbuf[2*TBH];
__device__ float g_cbuf[2*TBH];

// h bf16 hi/lo planes for scan MMA, layout [slot][t][chunk(8)][swizzled b*256+k*2]
__device__ __align__(128) bf16 g_hTh[(size_t)2*T*32768];
__device__ __align__(128) bf16 g_hTl[(size_t)2*T*32768];

// bf16-split pre-tiled planes for GEMMs
__device__ __align__(128) bf16 g_xbh[(size_t)B*T*DI], g_xbl[(size_t)B*T*DI];
__device__ __align__(128) bf16 g_hbh[(size_t)B*T*H],  g_hbl[(size_t)B*T*H];
__device__ __align__(128) bf16 g_w0h[(size_t)G4*DI],  g_w0l[(size_t)G4*DI];
__device__ __align__(128) bf16 g_wch[(size_t)3*G5*H], g_wcl[(size_t)3*G5*H];

// Two-level monotone barrier state
__device__ unsigned g_c1[8 * 64];
__device__ unsigned g_c0;
__device__ volatile unsigned g_gen;

__device__ __forceinline__ float sigf(float x) { return 1.0f / (1.0f + __expf(-x)); }
__device__ __forceinline__ unsigned smem_u32(const void* p) {
    return (unsigned)__cvta_generic_to_shared(p);
}

// ---- mbarrier / bulk-copy helpers ------------------------------------------
__device__ __forceinline__ void mbar_init(unsigned a, unsigned cnt) {
    asm volatile("mbarrier.init.shared.b64 [%0], %1;" :: "r"(a), "r"(cnt) : "memory");
}
__device__ __forceinline__ void mbar_expect(unsigned a, unsigned tx) {
    asm volatile("mbarrier.arrive.expect_tx.shared.b64 _, [%0], %1;" :: "r"(a), "r"(tx) : "memory");
}
__device__ __forceinline__ void mbar_wait(unsigned a, unsigned ph) {
    unsigned done = 0;
    while (!done) {
        asm volatile(
            "{\n\t.reg .pred p;\n\t"
            "mbarrier.try_wait.parity.acquire.cta.shared::cta.b64 p, [%1], %2;\n\t"
            "selp.b32 %0, 1, 0, p;\n\t}"
            : "=r"(done) : "r"(a), "r"(ph) : "memory");
        if (!done) __nanosleep(32);
    }
}
__device__ __forceinline__ void tma_bulk(unsigned dst, const void* src, unsigned bytes, unsigned mbar) {
    asm volatile("fence.proxy.async.shared::cta;" ::: "memory");
    asm volatile(
        "cp.async.bulk.shared::cluster.global.mbarrier::complete_tx::bytes [%0], [%1], %2, [%3];"
        :: "r"(dst), "l"(src), "r"(bytes), "r"(mbar) : "memory");
}

// ---- warp MMA helpers -------------------------------------------------------
__device__ __forceinline__ void ldsm4(unsigned* r, unsigned addr) {
    asm volatile("ldmatrix.sync.aligned.m8n8.x4.shared.b16 {%0,%1,%2,%3}, [%4];"
                 : "=r"(r[0]), "=r"(r[1]), "=r"(r[2]), "=r"(r[3]) : "r"(addr));
}
__device__ __forceinline__ void ldsm2(unsigned* r, unsigned addr) {
    asm volatile("ldmatrix.sync.aligned.m8n8.x2.shared.b16 {%0,%1}, [%2];"
                 : "=r"(r[0]), "=r"(r[1]) : "r"(addr));
}
__device__ __forceinline__ void mma16816(float* d, const unsigned* a, const unsigned* b) {
    asm volatile(
        "mma.sync.aligned.m16n8k16.row.col.f32.bf16.bf16.f32 "
        "{%0,%1,%2,%3}, {%4,%5,%6,%7}, {%8,%9}, {%0,%1,%2,%3};"
        : "+f"(d[0]), "+f"(d[1]), "+f"(d[2]), "+f"(d[3])
        : "r"(a[0]), "r"(a[1]), "r"(a[2]), "r"(a[3]), "r"(b[0]), "r"(b[1]));
}

static __device__ __forceinline__ unsigned SWZ(unsigned off) { return off ^ ((off >> 3) & 0x70); }

// ---------------------------------------------------------------------------
// conv_pack (unchanged R16)
// ---------------------------------------------------------------------------
__global__ __launch_bounds__(256) void conv_pack(
    const float* __restrict__ src, int ld, int logK, int logRT,
    bf16* __restrict__ hi, bf16* __restrict__ lo)
{
    size_t i = (size_t)blockIdx.x * 256 + threadIdx.x;
    int K = 1 << logK;
    size_t r = i >> logK;
    int k = (int)(i & (size_t)(K - 1));
    float v = src[r * (size_t)ld + k];
    int rb = (int)(r >> logRT);
    int rl = (int)(r & ((1 << logRT) - 1));
    int kc = k >> 6, kl = k & 63;
    unsigned off = SWZ((unsigned)(rl * 128 + kl * 2)) >> 1;
    size_t tile = ((size_t)rb * (K >> 6) + kc) * ((size_t)(1 << logRT) * 64);
    bf16 h = __float2bfloat16(v);
    hi[tile + off] = h;
    lo[tile + off] = __float2bfloat16(v - __bfloat162float(h));
}

// ---------------------------------------------------------------------------
// Warp-MMA GEMM (unchanged R16)
// ---------------------------------------------------------------------------
#define ATILE 8192
#define BTILE 4096
#define CHB 49152u
#define GSH 1024
#define GEMM_SMEM (GSH + 2*49152)

__global__ __launch_bounds__(256, 2) void gemm_mma(
    const bf16* __restrict__ Ah, const bf16* __restrict__ Al,
    const bf16* __restrict__ Bh, const bf16* __restrict__ Bl,
    const float* __restrict__ b0, const float* __restrict__ b1,
    float* __restrict__ C, int ldc, int nkc, int swapMT)
{
    extern __shared__ char smem[];
    const unsigned sb = smem_u32(smem);
    const int tid = threadIdx.x;
    const int lane = tid & 31, wid = tid >> 5;
    const int wm = wid >> 2, wn = wid & 3;
    const int nb = blockIdx.x, mb = blockIdx.y;
    const int n0 = nb * 64, m0 = mb * 128;

    if (tid < 64) {
        float bias = b0[n0 + tid] + (b1 ? b1[n0 + tid] : 0.0f);
        reinterpret_cast<float*>(smem + 64)[tid] = bias;
    }
    if (tid == 0) { mbar_init(sb + 0, 1); mbar_init(sb + 8, 1); }
    __syncthreads();

    const bf16* tAh = Ah + (size_t)mb * nkc * ATILE;
    const bf16* tAl = Al + (size_t)mb * nkc * ATILE;
    const bf16* tBh = Bh + (size_t)nb * nkc * BTILE;
    const bf16* tBl = Bl + (size_t)nb * nkc * BTILE;

    if (tid == 0) {
        mbar_expect(sb, CHB);
        tma_bulk(sb + GSH,         tAh, 16384, sb);
        tma_bulk(sb + GSH + 16384, tAl, 16384, sb);
        tma_bulk(sb + GSH + 32768, tBh, 8192,  sb);
        tma_bulk(sb + GSH + 40960, tBl, 8192,  sb);
    }

    const unsigned axor = (unsigned)(lane & 7) * 16;
    const unsigned ahalf = (unsigned)(lane >> 4) * 16;
    const int mi = lane >> 3;
    const unsigned bhalf = (unsigned)(mi & 1) * 16;
    const int brow = wn * 16 + (lane & 7) + (mi >> 1) * 8;
    unsigned aBase[4];
#pragma unroll
    for (int i = 0; i < 4; i++)
        aBase[i] = (unsigned)((wm * 64 + i * 16 + (lane & 15)) * 128);
    const unsigned bBase = (unsigned)(brow * 128);

    float d[4][2][4];
#pragma unroll
    for (int i = 0; i < 4; i++)
#pragma unroll
        for (int j = 0; j < 2; j++)
#pragma unroll
            for (int q = 0; q < 4; q++) d[i][j][q] = 0.0f;

    unsigned ph[2] = {0, 0};
    int cur = 0;
    for (int kci = 0; kci < nkc; kci++) {
        mbar_wait(sb + cur * 8, ph[cur]); ph[cur] ^= 1;
        __syncthreads();
        if (tid == 0 && kci + 1 < nkc) {
            int nx = cur ^ 1;
            unsigned db = sb + GSH + nx * 49152;
            mbar_expect(sb + nx * 8, CHB);
            tma_bulk(db,         tAh + (size_t)(kci + 1) * ATILE, 16384, sb + nx * 8);
            tma_bulk(db + 16384, tAl + (size_t)(kci + 1) * ATILE, 16384, sb + nx * 8);
            tma_bulk(db + 32768, tBh + (size_t)(kci + 1) * BTILE, 8192,  sb + nx * 8);
            tma_bulk(db + 40960, tBl + (size_t)(kci + 1) * BTILE, 8192,  sb + nx * 8);
        }
        const unsigned bAh = sb + GSH + cur * 49152;
        const unsigned bAl = bAh + 16384;
        const unsigned bBh = bAh + 32768;
        const unsigned bBl = bAh + 40960;
#pragma unroll
        for (int ks = 0; ks < 4; ks++) {
            const unsigned aoff = ((unsigned)ks * 32 + ahalf) ^ axor;
            const unsigned boff = ((unsigned)ks * 32 + bhalf) ^ axor;
            unsigned ah[4][4], al[4][4], bh[4], bl[4];
            ldsm4(bh, bBh + bBase + boff);
            ldsm4(bl, bBl + bBase + boff);
#pragma unroll
            for (int i = 0; i < 4; i++) {
                ldsm4(ah[i], bAh + aBase[i] + aoff);
                ldsm4(al[i], bAl + aBase[i] + aoff);
            }
#pragma unroll
            for (int i = 0; i < 4; i++)
#pragma unroll
                for (int j = 0; j < 2; j++) {
                    mma16816(d[i][j], ah[i], bh + j * 2);
                    mma16816(d[i][j], ah[i], bl + j * 2);
                    mma16816(d[i][j], al[i], bh + j * 2);
                }
        }
        cur ^= 1;
    }

    const float* bias = reinterpret_cast<const float*>(smem + 64);
    const int gid = lane >> 2, tig = lane & 3;
#pragma unroll
    for (int i = 0; i < 4; i++) {
        int mA = m0 + wm * 64 + i * 16 + gid;
        int mB = mA + 8;
        int rowA = swapMT ? ((mA & 255) * 32 + (mA >> 8)) : mA;
        int rowB = swapMT ? ((mB & 255) * 32 + (mB >> 8)) : mB;
#pragma unroll
        for (int j = 0; j < 2; j++) {
            int nl = wn * 16 + j * 8 + tig * 2;
            float2 vA; vA.x = d[i][j][0] + bias[nl]; vA.y = d[i][j][1] + bias[nl + 1];
            float2 vB; vB.x = d[i][j][2] + bias[nl]; vB.y = d[i][j][3] + bias[nl + 1];
            *reinterpret_cast<float2*>(C + (size_t)rowA * ldc + n0 + nl) = vA;
            *reinterpret_cast<float2*>(C + (size_t)rowB * ldc + n0 + nl) = vB;
        }
    }
}

// ---------------------------------------------------------------------------
// MMA-based persistent scans. W resident in smem (bf16 hi/lo, XOR-swizzled);
// h staged per 128-k chunk (bf16 hi/lo) via cp.async.bulk, 4-buffer pipeline.
// Warp = (ks8 in 8, mh in 2): 1 m-tile(16b) x NG n-tiles(8) x k16 per chunk.
// ---------------------------------------------------------------------------
__device__ __forceinline__ void scan_grid_bar(int grp8, unsigned gbase, unsigned& bar_i)
{
    __syncthreads();
    if (threadIdx.x == 0) {
        __threadfence();
        unsigned v = atomicAdd(&g_c1[grp8 * 64], 1u);
        if ((v & 15u) == 15u) {
            unsigned r = atomicAdd(&g_c0, 1u);
            if ((r & 7u) == 7u) { __threadfence(); g_gen = g_gen + 1; }
        }
        bar_i++;
        while (g_gen - gbase < bar_i) __nanosleep(32);
        __threadfence();
    }
    __syncthreads();
}

template<int NG>
__device__ __forceinline__ void step_mma(
    unsigned sb, unsigned wsm, unsigned wlo, unsigned bufs,
    const bf16* srcH, const bf16* srcL,
    float (&d)[NG][4], unsigned* ph,
    unsigned aoff, unsigned bn, unsigned bkhalf, int ks8, int tid)
{
    if (tid == 0) {
#pragma unroll
        for (int c = 0; c < 4; c++) {
            mbar_expect(sb + c * 8, 16384u);
            tma_bulk(bufs + c * 16384, srcH + c * 4096, 8192u, sb + c * 8);
            tma_bulk(bufs + c * 16384 + 8192, srcL + c * 4096, 8192u, sb + c * 8);
        }
    }
#pragma unroll
    for (int c = 0; c < 8; c++) {
        const int bi = c & 3;
        mbar_wait(sb + bi * 8, ph[bi]); ph[bi] ^= 1;
        const unsigned hb_ = bufs + bi * 16384;
        unsigned ah[4], al[4];
        ldsm4(ah, hb_ + aoff);
        ldsm4(al, hb_ + 8192 + aoff);
        const unsigned bkb = (unsigned)c * 256 + (unsigned)ks8 * 32 + bkhalf;
#pragma unroll
        for (int nt = 0; nt < NG; nt++) {
            unsigned n = (unsigned)nt * 8 + bn;
            unsigned ba = wsm + n * 2048 + (bkb ^ ((n & 7) * 16));
            unsigned bh[2], bl[2];
            ldsm2(bh, ba);
            ldsm2(bl, ba + wlo);
            mma16816(d[nt], ah, bh);
            mma16816(d[nt], al, bh);
            mma16816(d[nt], ah, bl);
        }
        __syncthreads();
        if (tid == 0 && c < 4) {
            mbar_expect(sb + bi * 8, 16384u);
            tma_bulk(bufs + bi * 16384, srcH + (c + 4) * 4096, 8192u, sb + bi * 8);
            tma_bulk(bufs + bi * 16384 + 8192, srcL + (c + 4) * 4096, 8192u, sb + bi * 8);
        }
    }
    __syncthreads();
}

#define SC0_W 65536
#define SC0_SMEM (1024 + 2*SC0_W + 65536)
#define SCC_W 81920
#define SCC_SMEM (1024 + 2*SCC_W + 65536)

__global__ __launch_bounds__(512) void lstm0_scan(const float* __restrict__ Whh)
{
    extern __shared__ char smc[];
    const unsigned sb = smem_u32(smc);
    const unsigned wsm = sb + 1024;
    const unsigned bufs = sb + 1024 + 2 * SC0_W;
    float* red = reinterpret_cast<float*>(smc + 1024 + 2 * SC0_W);
    float2* red2 = reinterpret_cast<float2*>(red);

    const int tid = threadIdx.x;
    const int lane = tid & 31, wid = tid >> 5;
    const int ks8 = wid & 7, mh = wid >> 3;
    const int jbase = blockIdx.x * 8, grp8 = blockIdx.x & 7;
    const int pj8 = tid & 7, pbb = tid >> 3;
    const int pj = jbase + pj8;
    float creg = 0.0f;
    unsigned ph[4] = {0, 0, 0, 0};
    unsigned gbase = 0, bar_i = 0;

    if (tid == 0) {
        gbase = g_gen;
#pragma unroll
        for (int c = 0; c < 4; c++) mbar_init(sb + c * 8, 1);
    }
    // W -> smem bf16 split, row pitch 2048B, XOR (r&7)*16
    for (int i = tid; i < 32 * 1024; i += 512) {
        int r = i >> 10, k = i & 1023;
        int grow = ((r >> 3) << 10) + jbase + (r & 7);
        float v = Whh[(size_t)grow * H + k];
        bf16 h = __float2bfloat16(v);
        bf16 l = __float2bfloat16(v - __bfloat162float(h));
        unsigned byte = (unsigned)r * 2048 + (((unsigned)k * 2) ^ ((unsigned)(r & 7) * 16));
        *reinterpret_cast<bf16*>(smc + 1024 + byte) = h;
        *reinterpret_cast<bf16*>(smc + 1024 + SC0_W + byte) = l;
    }
    __syncthreads();

    const unsigned arow = (unsigned)(mh * 16 + (lane & 15));
    const unsigned aoff = (arow * 256 + (unsigned)ks8 * 32 + (unsigned)(lane >> 4) * 16) ^ ((arow & 7) * 16);
    const unsigned bn = (unsigned)(lane & 7);
    const unsigned bkhalf = (unsigned)((lane >> 3) & 1) * 16;
    const int gid = lane >> 2, a4 = lane & 3;

    for (int t = 0; t < T; t++) {
        float pg0 = 0, pg1 = 0, pg2 = 0, pg3 = 0;
        size_t idx = 0;
        if (tid < 256) {
            const float* xp = g_pre + ((size_t)t * B + pbb) * G4 + pj;
            pg0 = xp[0]; pg1 = xp[H]; pg2 = xp[2*H]; pg3 = xp[3*H];
            idx = ((size_t)t * B + pbb) * H + pj;
        }

        if (t > 0) {
            float d[4][4];
#pragma unroll
            for (int nt = 0; nt < 4; nt++)
#pragma unroll
                for (int q = 0; q < 4; q++) d[nt][q] = 0.0f;

            const bf16* srcH = g_hTh + (size_t)(t - 1) * 32768;
            const bf16* srcL = g_hTl + (size_t)(t - 1) * 32768;
            step_mma<4>(sb, wsm, SC0_W, bufs, srcH, srcL, d, ph, aoff, bn, bkhalf, ks8, tid);

#pragma unroll
            for (int nt = 0; nt < 4; nt++) {
                int b0 = mh * 16 + gid;
                red2[(ks8 * 32 + b0) * 16 + nt * 4 + a4]     = make_float2(d[nt][0], d[nt][1]);
                red2[(ks8 * 32 + b0 + 8) * 16 + nt * 4 + a4] = make_float2(d[nt][2], d[nt][3]);
            }
            __syncthreads();
        }

        if (tid < 256) {
            float sg[4] = {0, 0, 0, 0};
            if (t > 0) {
#pragma unroll
                for (int g = 0; g < 4; g++) {
                    float s = 0.0f;
#pragma unroll
                    for (int w = 0; w < 8; w++)
                        s += red[(w * 32 + pbb) * 32 + g * 8 + pj8];
                    sg[g] = s;
                }
            }
            float gi = sg[0] + pg0, gf = sg[1] + pg1, gg = sg[2] + pg2, go = sg[3] + pg3;
            float cc = sigf(gf) * creg + sigf(gi) * tanhf(gg);
            float hh = sigf(go) * tanhf(cc);
            creg = cc;
            g_hbuf[idx] = hh;
            g_cbuf[idx] = cc;
            bf16 bh = __float2bfloat16(hh);
            bf16 bl = __float2bfloat16(hh - __bfloat162float(bh));
            unsigned byte = ((unsigned)pbb * 256 + (unsigned)(pj & 127) * 2) ^ ((unsigned)(pbb & 7) * 16);
            size_t ho = (size_t)t * 32768 + (size_t)(pj >> 7) * 4096 + (byte >> 1);
            g_hTh[ho] = bh;
            g_hTl[ho] = bl;
        }

        if (t < T - 1) scan_grid_bar(grp8, gbase, bar_i);
    }
}

__global__ __launch_bounds__(512) void ca_scan(const float* __restrict__ Wp, int src_s, int dst)
{
    extern __shared__ char smc[];
    const unsigned sb = smem_u32(smc);
    const unsigned wsm = sb + 1024;
    const unsigned bufs = sb + 1024 + 2 * SCC_W;
    float* red = reinterpret_cast<float*>(smc + 1024 + 2 * SCC_W);
    float2* red2 = reinterpret_cast<float2*>(red);

    const int tid = threadIdx.x;
    const int lane = tid & 31, wid = tid >> 5;
    const int ks8 = wid & 7, mh = wid >> 3;
    const int jbase = blockIdx.x * 8, grp8 = blockIdx.x & 7;
    const int pj8 = tid & 7, pbb = tid >> 3;
    const int pj = jbase + pj8;
    float creg = 0.0f;
    unsigned ph[4] = {0, 0, 0, 0};
    unsigned gbase = 0, bar_i = 0;

    if (tid == 0) {
        gbase = g_gen;
#pragma unroll
        for (int c = 0; c < 4; c++) mbar_init(sb + c * 8, 1);
    }
    for (int i = tid; i < 40 * 1024; i += 512) {
        int r = i >> 10, k = i & 1023;
        int grow = (r >> 3) * H + jbase + (r & 7);
        float v = Wp[(size_t)grow * (2 * H) + k];
        bf16 h = __float2bfloat16(v);
        bf16 l = __float2bfloat16(v - __bfloat162float(h));
        unsigned byte = (unsigned)r * 2048 + (((unsigned)k * 2) ^ ((unsigned)(r & 7) * 16));
        *reinterpret_cast<bf16*>(smc + 1024 + byte) = h;
        *reinterpret_cast<bf16*>(smc + 1024 + SCC_W + byte) = l;
    }
    __syncthreads();

    const unsigned arow = (unsigned)(mh * 16 + (lane & 15));
    const unsigned aoff = (arow * 256 + (unsigned)ks8 * 32 + (unsigned)(lane >> 4) * 16) ^ ((arow & 7) * 16);
    const unsigned bn = (unsigned)(lane & 7);
    const unsigned bkhalf = (unsigned)((lane >> 3) & 1) * 16;
    const int gid = lane >> 2, a4 = lane & 3;

    for (int t = 0; t < T; t++) {
        float pg0 = 0, pg1 = 0, pg2 = 0, pg3 = 0, pg4 = 0, cl = 0;
        size_t idx = 0;
        if (tid < 256) {
            const float* pre = g_pre + ((size_t)t * B + pbb) * G5 + pj;
            pg0 = pre[0]; pg1 = pre[H]; pg2 = pre[2*H]; pg3 = pre[3*H]; pg4 = pre[4*H];
            idx = ((size_t)t * B + pbb) * H + pj;
            cl = g_cbuf[(size_t)src_s * TBH + idx];
        }

        if (t > 0) {
            float d[5][4];
#pragma unroll
            for (int nt = 0; nt < 5; nt++)
#pragma unroll
                for (int q = 0; q < 4; q++) d[nt][q] = 0.0f;

            const bf16* srcH = g_hTh + ((size_t)dst * T + (t - 1)) * 32768;
            const bf16* srcL = g_hTl + ((size_t)dst * T + (t - 1)) * 32768;
            step_mma<5>(sb, wsm, SCC_W, bufs, srcH, srcL, d, ph, aoff, bn, bkhalf, ks8, tid);

#pragma unroll
            for (int nt = 0; nt < 5; nt++) {
                int b0 = mh * 16 + gid;
                red2[(ks8 * 32 + b0) * 20 + nt * 4 + a4]     = make_float2(d[nt][0], d[nt][1]);
                red2[(ks8 * 32 + b0 + 8) * 20 + nt * 4 + a4] = make_float2(d[nt][2], d[nt][3]);
            }
            __syncthreads();
        }

        if (tid < 256) {
            float sg[5] = {0, 0, 0, 0, 0};
            if (t > 0) {
#pragma unroll
                for (int g = 0; g < 5; g++) {
                    float s = 0.0f;
#pragma unroll
                    for (int w = 0; w < 8; w++)
                        s += red[(w * 32 + pbb) * 40 + g * 8 + pj8];
                    sg[g] = s;
                }
            }
            float gi  = sg[0] + pg0;
            float gfp = sg[1] + pg1;
            float gfl = sg[2] + pg2;
            float gu  = sg[3] + pg3;
            float go  = sg[4] + pg4;
            float cc = creg * sigf(gfp + 1.0f) + cl * sigf(gfl + 1.0f) + tanhf(gu) * sigf(gi);
            float hh = sigf(go) * tanhf(cc);
            creg = cc;
            g_hbuf[(size_t)dst * TBH + idx] = hh;
            g_cbuf[(size_t)dst * TBH + idx] = cc;
            bf16 bh = __float2bfloat16(hh);
            bf16 bl = __float2bfloat16(hh - __bfloat162float(bh));
            unsigned byte = ((unsigned)pbb * 256 + (unsigned)(pj & 127) * 2) ^ ((unsigned)(pbb & 7) * 16);
            size_t ho = ((size_t)dst * T + t) * 32768 + (size_t)(pj >> 7) * 4096 + (byte >> 1);
            g_hTh[ho] = bh;
            g_hTl[ho] = bl;
        }

        if (t < T - 1) scan_grid_bar(grp8, gbase, bar_i);
    }
}

// ---------------------------------------------------------------------------
__global__ __launch_bounds__(256) void finalize(int fin, float* __restrict__ out)
{
    size_t gid = (size_t)blockIdx.x * 256 + threadIdx.x;
    int j = (int)(gid & (H - 1));
    int bt = (int)(gid >> 10);
    int t = bt & (T - 1);
    int b = bt >> 8;
    size_t srci = ((size_t)t * B + b) * H + j;
    out[gid]       = g_hbuf[(size_t)fin * TBH + srci];
    out[TBH + gid] = g_cbuf[(size_t)fin * TBH + srci];
}

// ---------------------------------------------------------------------------
extern "C" void kernel_launch(void* const* d_in, const int* in_sizes, int n_in,
                              void* d_out, int out_size)
{
    (void)in_sizes; (void)n_in; (void)out_size;
    const float* inputs = (const float*)d_in[0];
    const float* W_ih0  = (const float*)d_in[1];
    const float* W_hh0  = (const float*)d_in[2];
    const float* b_ih0  = (const float*)d_in[3];
    const float* b_hh0  = (const float*)d_in[4];
    const float* W_ca   = (const float*)d_in[5];
    const float* b_ca   = (const float*)d_in[6];
    float* out = (float*)d_out;

    float* pre = nullptr;
    float* hb  = nullptr;
    cudaGetSymbolAddress((void**)&pre, g_pre);
    cudaGetSymbolAddress((void**)&hb,  g_hbuf);
    bf16 *xbh, *xbl, *hbh, *hbl, *w0h, *w0l, *wch, *wcl;
    cudaGetSymbolAddress((void**)&xbh, g_xbh);  cudaGetSymbolAddress((void**)&xbl, g_xbl);
    cudaGetSymbolAddress((void**)&hbh, g_hbh);  cudaGetSymbolAddress((void**)&hbl, g_hbl);
    cudaGetSymbolAddress((void**)&w0h, g_w0h);  cudaGetSymbolAddress((void**)&w0l, g_w0l);
    cudaGetSymbolAddress((void**)&wch, g_wch);  cudaGetSymbolAddress((void**)&wcl, g_wcl);

    cudaFuncSetAttribute(lstm0_scan, cudaFuncAttributeMaxDynamicSharedMemorySize, SC0_SMEM);
    cudaFuncSetAttribute(ca_scan,    cudaFuncAttributeMaxDynamicSharedMemorySize, SCC_SMEM);
    cudaFuncSetAttribute(gemm_mma,   cudaFuncAttributeMaxDynamicSharedMemorySize, GEMM_SMEM);

    conv_pack<<<(B * T * DI) / 256, 256>>>(inputs, DI, 9, 7, xbh, xbl);
    conv_pack<<<(G4 * DI) / 256, 256>>>(W_ih0, DI, 9, 6, w0h, w0l);
    for (int l = 0; l < 3; l++)
        conv_pack<<<(G5 * H) / 256, 256>>>(W_ca + (size_t)l * G5 * (2 * H), 2 * H, 10, 6,
                                           wch + (size_t)l * G5 * H, wcl + (size_t)l * G5 * H);

    gemm_mma<<<dim3(G4 / 64, (B * T) / 128), 256, GEMM_SMEM>>>(
        xbh, xbl, w0h, w0l, b_ih0, b_hh0, pre, G4, DI / 64, 1);
    lstm0_scan<<<NBLK, 512, SC0_SMEM>>>(W_hh0);

    int src = 0;
    for (int l = 0; l < 3; l++) {
        int dst = 1 - src;
        conv_pack<<<(B * T * H) / 256, 256>>>(hb + (size_t)src * TBH, H, 10, 7, hbh, hbl);
        gemm_mma<<<dim3(G5 / 64, (B * T) / 128), 256, GEMM_SMEM>>>(
            hbh, hbl, wch + (size_t)l * G5 * H, wcl + (size_t)l * G5 * H,
            b_ca + (size_t)l * G5, nullptr, pre, G5, H / 64, 0);
        ca_scan<<<NBLK, 512, SCC_SMEM>>>(W_ca + (size_t)l * G5 * (2 * H) + H, src, dst);
        src = dst;
    }

    finalize<<<(int)(TBH / 256), 256>>>(src, out);
}